// round 3
// baseline (speedup 1.0000x reference)
#include <cuda_runtime.h>
#include <cuda_bf16.h>
#include <cstdint>

#define MAXN 131072
#define MAXE 655360
#define GMAX 1024

// ---------------- static scratch (no allocations allowed) ----------------
__device__ float          g_h[(size_t)MAXN * 128];        // residual stream (fp32)
__device__ __nv_bfloat16  g_t[(size_t)MAXN * 128];        // GEMM A operand (bf16)
__device__ __nv_bfloat16  g_esort[(size_t)MAXE * 128];    // bond embeds, CSR order, bf16
__device__ int            g_srcs[MAXE];
__device__ int            g_eid[MAXE];
__device__ int            g_rowptr[MAXN + 1];
__device__ int            g_deg[MAXN];
__device__ int            g_incl[MAXN];
__device__ int            g_cursor[MAXN];
__device__ int            g_bsum[256];
__device__ __nv_bfloat16  g_Wt[8 * 128 * 128];            // Wt[l][n][k] = W[l][k][n], bf16
__device__ float          g_bnsum[128];
__device__ float          g_bnsq[128];
__device__ float          g_bnscale[128];
__device__ float          g_bnshift[128];
__device__ float          g_acc[(size_t)GMAX * 128];
__device__ int            g_cnt[GMAX];

// ---------------- helpers ----------------
__device__ __forceinline__ uint32_t smem_u32(const void* p) {
    uint32_t a;
    asm("{ .reg .u64 t; cvta.to.shared.u64 t, %1; cvt.u32.u64 %0, t; }" : "=r"(a) : "l"(p));
    return a;
}

#define LDMATRIX_X4(r0, r1, r2, r3, addr) \
    asm volatile("ldmatrix.sync.aligned.m8n8.x4.shared.b16 {%0,%1,%2,%3}, [%4];" \
                 : "=r"(r0), "=r"(r1), "=r"(r2), "=r"(r3) : "r"(addr))

#define MMA_BF16(c, a0, a1, a2, a3, b0, b1) \
    asm volatile("mma.sync.aligned.m16n8k16.row.col.f32.bf16.bf16.f32 " \
                 "{%0,%1,%2,%3}, {%4,%5,%6,%7}, {%8,%9}, {%0,%1,%2,%3};" \
                 : "+f"((c)[0]), "+f"((c)[1]), "+f"((c)[2]), "+f"((c)[3]) \
                 : "r"(a0), "r"(a1), "r"(a2), "r"(a3), "r"(b0), "r"(b1))

// ---------------- encoders + CSR ----------------
__global__ void k_h0(const int* __restrict__ x, const float* __restrict__ aemb, int N) {
    int c = threadIdx.x;
    for (int n = blockIdx.x; n < N; n += gridDim.x) {
        float s = 0.f;
#pragma unroll
        for (int f = 0; f < 9; f++) {
            int xi = __ldg(x + n * 9 + f);
            s += __ldg(aemb + ((size_t)f * 64 + xi) * 128 + c);
        }
        g_h[(size_t)n * 128 + c] = s;
    }
}

__global__ void k_zero_prep(int N) {
    for (int i = blockIdx.x * blockDim.x + threadIdx.x; i < N; i += gridDim.x * blockDim.x) {
        g_deg[i] = 0;
        g_cursor[i] = 0;
    }
}

__global__ void k_hist(const int* __restrict__ ei, int E) {
    int e = blockIdx.x * blockDim.x + threadIdx.x;
    if (e < E) atomicAdd(g_deg + ei[E + e], 1);
}

__global__ void k_scan1(int N) {
    __shared__ int sm[1024];
    int i = blockIdx.x * 1024 + threadIdx.x;
    int v = (i < N) ? g_deg[i] : 0;
    sm[threadIdx.x] = v;
    __syncthreads();
    for (int off = 1; off < 1024; off <<= 1) {
        int t = (threadIdx.x >= off) ? sm[threadIdx.x - off] : 0;
        __syncthreads();
        if (threadIdx.x >= off) sm[threadIdx.x] += t;
        __syncthreads();
    }
    if (i < N) g_incl[i] = sm[threadIdx.x];
    if (threadIdx.x == 1023) g_bsum[blockIdx.x] = sm[1023];
}

__global__ void k_scan2(int nb) {
    __shared__ int sm[256];
    int t = threadIdx.x;
    int v = (t < nb) ? g_bsum[t] : 0;
    sm[t] = v;
    __syncthreads();
    for (int off = 1; off < 256; off <<= 1) {
        int u = (t >= off) ? sm[t - off] : 0;
        __syncthreads();
        if (t >= off) sm[t] += u;
        __syncthreads();
    }
    if (t < nb) g_bsum[t] = sm[t] - v;  // exclusive block offsets
}

__global__ void k_scan3(int N, int E) {
    int i = blockIdx.x * 1024 + threadIdx.x;
    if (i < N) g_rowptr[i] = g_incl[i] - g_deg[i] + g_bsum[blockIdx.x];
    if (i == 0) g_rowptr[N] = E;
}

__global__ void k_scatter(const int* __restrict__ ei, int E) {
    int e = blockIdx.x * blockDim.x + threadIdx.x;
    if (e >= E) return;
    int d = ei[E + e];
    int pos = g_rowptr[d] + atomicAdd(g_cursor + d, 1);
    g_srcs[pos] = ei[e];
    g_eid[pos] = e;
}

__global__ void k_eembed(const int* __restrict__ ea, const float* __restrict__ bemb, int E) {
    int c = threadIdx.x;
    for (int p = blockIdx.x; p < E; p += gridDim.x) {
        int e = g_eid[p];
        float s = 0.f;
#pragma unroll
        for (int f = 0; f < 3; f++) {
            int ai = __ldg(ea + e * 3 + f);
            s += __ldg(bemb + ((size_t)f * 8 + ai) * 128 + c);
        }
        g_esort[(size_t)p * 128 + c] = __float2bfloat16(s);
    }
}

__global__ void k_convW(const float* __restrict__ w, int L) {
    int i = blockIdx.x * blockDim.x + threadIdx.x;
    int tot = L * 16384;
    if (i < tot) {
        int l = i >> 14, r = i & 16383, n = r >> 7, k = r & 127;
        g_Wt[i] = __float2bfloat16(w[(l << 14) + (k << 7) + n]);  // Wt[l][n][k] = W[l][k][n]
    }
}

// ---------------- BatchNorm stats ----------------
__global__ void k_bnzero() {
    int c = threadIdx.x;
    g_bnsum[c] = 0.f;
    g_bnsq[c] = 0.f;
}

__global__ void k_bnstats(int N) {
    int c = threadIdx.x;
    float s = 0.f, q = 0.f;
    for (int n = blockIdx.x; n < N; n += gridDim.x) {
        float v = g_h[(size_t)n * 128 + c];
        s += v;
        q = fmaf(v, v, q);
    }
    atomicAdd(g_bnsum + c, s);
    atomicAdd(g_bnsq + c, q);
}

__global__ void k_bnfinal(const float* __restrict__ gammas, const float* __restrict__ betas,
                          int l, int N) {
    int c = threadIdx.x;
    float invN = 1.f / (float)N;
    float mu = g_bnsum[c] * invN;
    float var = g_bnsq[c] * invN - mu * mu;
    float inv = rsqrtf(var + 1e-5f);
    float scv = inv * gammas[l * 128 + c];
    g_bnscale[c] = scv;
    g_bnshift[c] = betas[l * 128 + c] - mu * scv;
}

// ---------------- softmax aggregation (warp per node) ----------------
__device__ __forceinline__ void smupd(float& m, float& s, float& w, float msg, float tt) {
    float lg = msg * tt;
    float mn = fmaxf(m, lg);
    float e = __expf(fminf(m, lg) - mn);
    if (lg > m) { s = fmaf(s, e, 1.f); w = fmaf(w, e, msg); }
    else        { s = s + e;           w = fmaf(e, msg, w); }
    m = mn;
}

__global__ void __launch_bounds__(128) k_agg(const float* __restrict__ ts, int l,
                                             int use_bn, int N) {
    int gw = (blockIdx.x << 2) + (threadIdx.x >> 5);
    if (gw >= N) return;
    int lane = threadIdx.x & 31;
    int c0 = lane << 2;

    float sc0 = 1.f, sc1 = 1.f, sc2 = 1.f, sc3 = 1.f;
    float sh0 = 0.f, sh1 = 0.f, sh2 = 0.f, sh3 = 0.f;
    if (use_bn) {
        float4 sc = *(const float4*)(g_bnscale + c0);
        float4 sh = *(const float4*)(g_bnshift + c0);
        sc0 = sc.x; sc1 = sc.y; sc2 = sc.z; sc3 = sc.w;
        sh0 = sh.x; sh1 = sh.y; sh2 = sh.z; sh3 = sh.w;
    }
    float tt = __ldg(ts + l);

    float4 hv = *(const float4*)(g_h + (size_t)gw * 128 + c0);
    float hin0, hin1, hin2, hin3;
    if (use_bn) {
        hin0 = fmaxf(fmaf(hv.x, sc0, sh0), 0.f);
        hin1 = fmaxf(fmaf(hv.y, sc1, sh1), 0.f);
        hin2 = fmaxf(fmaf(hv.z, sc2, sh2), 0.f);
        hin3 = fmaxf(fmaf(hv.w, sc3, sh3), 0.f);
    } else {
        hin0 = hv.x; hin1 = hv.y; hin2 = hv.z; hin3 = hv.w;
    }

    int p0 = __ldg(g_rowptr + gw), p1 = __ldg(g_rowptr + gw + 1);
    float m0 = -3.0e38f, m1 = -3.0e38f, m2 = -3.0e38f, m3 = -3.0e38f;
    float s0 = 0.f, s1 = 0.f, s2 = 0.f, s3 = 0.f;
    float w0 = 0.f, w1 = 0.f, w2 = 0.f, w3 = 0.f;

    for (int p = p0; p < p1; p++) {
        int si = __ldg(g_srcs + p);
        float4 hs = *(const float4*)(g_h + (size_t)si * 128 + c0);
        uint2 eu = *(const uint2*)(g_esort + (size_t)p * 128 + c0);
        __nv_bfloat162 e01 = *reinterpret_cast<__nv_bfloat162*>(&eu.x);
        __nv_bfloat162 e23 = *reinterpret_cast<__nv_bfloat162*>(&eu.y);
        float2 f01 = __bfloat1622float2(e01);
        float2 f23 = __bfloat1622float2(e23);
        if (use_bn) {
            hs.x = fmaxf(fmaf(hs.x, sc0, sh0), 0.f);
            hs.y = fmaxf(fmaf(hs.y, sc1, sh1), 0.f);
            hs.z = fmaxf(fmaf(hs.z, sc2, sh2), 0.f);
            hs.w = fmaxf(fmaf(hs.w, sc3, sh3), 0.f);
        }
        float q0 = fmaxf(hs.x + f01.x, 0.f) + 1e-7f;
        float q1 = fmaxf(hs.y + f01.y, 0.f) + 1e-7f;
        float q2 = fmaxf(hs.z + f23.x, 0.f) + 1e-7f;
        float q3 = fmaxf(hs.w + f23.y, 0.f) + 1e-7f;
        smupd(m0, s0, w0, q0, tt);
        smupd(m1, s1, w1, q1, tt);
        smupd(m2, s2, w2, q2, tt);
        smupd(m3, s3, w3, q3, tt);
    }

    float o0 = hin0 + w0 / (s0 + 1e-16f);
    float o1 = hin1 + w1 / (s1 + 1e-16f);
    float o2 = hin2 + w2 / (s2 + 1e-16f);
    float o3 = hin3 + w3 / (s3 + 1e-16f);

    __nv_bfloat162 t01 = __floats2bfloat162_rn(o0, o1);
    __nv_bfloat162 t23 = __floats2bfloat162_rn(o2, o3);
    uint2 st;
    st.x = *reinterpret_cast<uint32_t*>(&t01);
    st.y = *reinterpret_cast<uint32_t*>(&t23);
    *(uint2*)(g_t + (size_t)gw * 128 + c0) = st;
}

// ---------------- mma.sync GEMM: h_new = t @ W^T (+b) (+h_old) ----------------
// A = g_t [128 nodes x 128 K] bf16, B = g_Wt[l] [128 n x 128 k] bf16 (both K-major)
// smem tiles with 272B row stride (128 bf16 + 8 skew) -> conflict-free ldmatrix
#define GEMM_SMEM (2 * 128 * 272)

__global__ void __launch_bounds__(256) k_gemm(const float* __restrict__ conv_b,
                                              int l, int add_res, int N) {
    extern __shared__ char smem[];
    char* sA = smem;
    char* sB = smem + 128 * 272;
    int tid = threadIdx.x;
    int node0 = blockIdx.x * 128;

    const uint4* asrc = (const uint4*)(g_t + (size_t)node0 * 128);
    const uint4* bsrc = (const uint4*)(g_Wt + (size_t)l * 16384);
#pragma unroll
    for (int i = tid; i < 2048; i += 256) {
        int row = i >> 4, cq = i & 15;
        *(uint4*)(sA + row * 272 + cq * 16) = asrc[i];
        *(uint4*)(sB + row * 272 + cq * 16) = bsrc[i];
    }
    __syncthreads();

    int wid = tid >> 5, lane = tid & 31;
    int wm = wid >> 1, wn = wid & 1;           // 4 x 2 warp grid
    uint32_t sab = smem_u32(sA), sbb = smem_u32(sB);

    float acc[2][8][4];
#pragma unroll
    for (int mt = 0; mt < 2; mt++)
#pragma unroll
        for (int nt = 0; nt < 8; nt++)
#pragma unroll
            for (int q = 0; q < 4; q++) acc[mt][nt][q] = 0.f;

    int lrow = lane & 15, lhalf = (lane >> 4) << 3;

#pragma unroll
    for (int ks = 0; ks < 8; ks++) {
        int k0 = ks * 16;
        uint32_t a[2][4];
#pragma unroll
        for (int mt = 0; mt < 2; mt++) {
            int r = wm * 32 + mt * 16 + lrow;
            uint32_t addr = sab + r * 272 + (k0 + lhalf) * 2;
            LDMATRIX_X4(a[mt][0], a[mt][1], a[mt][2], a[mt][3], addr);
        }
        uint32_t b[4][4];
#pragma unroll
        for (int nq = 0; nq < 4; nq++) {
            int nr = wn * 64 + nq * 16 + lrow;
            uint32_t addr = sbb + nr * 272 + (k0 + lhalf) * 2;
            LDMATRIX_X4(b[nq][0], b[nq][1], b[nq][2], b[nq][3], addr);
        }
#pragma unroll
        for (int mt = 0; mt < 2; mt++)
#pragma unroll
            for (int nq = 0; nq < 4; nq++) {
                MMA_BF16(acc[mt][nq * 2 + 0], a[mt][0], a[mt][1], a[mt][2], a[mt][3],
                         b[nq][0], b[nq][2]);
                MMA_BF16(acc[mt][nq * 2 + 1], a[mt][0], a[mt][1], a[mt][2], a[mt][3],
                         b[nq][1], b[nq][3]);
            }
    }

    // epilogue: bias (+ residual), write fp32 h
    int qrow = lane >> 2, qcol = (lane & 3) * 2;
#pragma unroll
    for (int mt = 0; mt < 2; mt++) {
#pragma unroll
        for (int nt = 0; nt < 8; nt++) {
            int col = wn * 64 + nt * 8 + qcol;
            float2 bv = *(const float2*)(conv_b + l * 128 + col);
            int row0 = node0 + wm * 32 + mt * 16 + qrow;
#pragma unroll
            for (int hh = 0; hh < 2; hh++) {
                int row = row0 + hh * 8;
                if (row < N) {
                    float* dst = g_h + (size_t)row * 128 + col;
                    float vx = acc[mt][nt][hh * 2 + 0] + bv.x;
                    float vy = acc[mt][nt][hh * 2 + 1] + bv.y;
                    if (add_res) {
                        float2 r = *(const float2*)dst;
                        vx += r.x; vy += r.y;
                    }
                    float2 o; o.x = vx; o.y = vy;
                    *(float2*)dst = o;
                }
            }
        }
    }
}

// ---------------- pooling + head ----------------
__global__ void k_poolzero(int G) {
    int i = blockIdx.x * blockDim.x + threadIdx.x;
    if (i < G * 128) g_acc[i] = 0.f;
    if (i < G) g_cnt[i] = 0;
}

__global__ void k_pool(const int* __restrict__ batch, int N, int nlen) {
    int c = threadIdx.x;
    int n0 = blockIdx.x * nlen, n1 = min(N, n0 + nlen);
    if (n0 >= n1) return;
    float sc = g_bnscale[c], sh = g_bnshift[c];
    int cur = __ldg(batch + n0);
    float acc = 0.f;
    int cnt = 0;
    for (int n = n0; n < n1; n++) {
        int gg = __ldg(batch + n);
        if (gg != cur) {
            atomicAdd(g_acc + (size_t)cur * 128 + c, acc);
            if (c == 0) atomicAdd(g_cnt + cur, cnt);
            acc = 0.f; cnt = 0; cur = gg;
        }
        float v = fmaxf(fmaf(g_h[(size_t)n * 128 + c], sc, sh), 0.f);
        acc += v;
        cnt++;
    }
    atomicAdd(g_acc + (size_t)cur * 128 + c, acc);
    if (c == 0) atomicAdd(g_cnt + cur, cnt);
}

__global__ void k_final(const float* __restrict__ fw, const float* __restrict__ fb,
                        const float* __restrict__ beta, const float* __restrict__ rf,
                        float* __restrict__ out, int G) {
    int wid = threadIdx.x >> 5, lane = threadIdx.x & 31;
    int g = blockIdx.x * 4 + wid;
    if (g >= G) return;
    float4 a = ((const float4*)(g_acc + (size_t)g * 128))[lane];
    float4 w = ((const float4*)fw)[lane];
    float dot = a.x * w.x + a.y * w.y + a.z * w.z + a.w * w.w;
#pragma unroll
    for (int o = 16; o > 0; o >>= 1) dot += __shfl_down_sync(0xFFFFFFFFu, dot, o);
    if (lane == 0) {
        float cntf = fmaxf((float)g_cnt[g], 1.f);
        float pred = dot / cntf + fb[0];
        float sg = 1.f / (1.f + __expf(-pred));
        float b = beta[0];
        out[g] = (1.f - b) * sg + b * rf[g];
    }
}

// ---------------- launch ----------------
extern "C" void kernel_launch(void* const* d_in, const int* in_sizes, int n_in,
                              void* d_out, int out_size) {
    const int*   x      = (const int*)d_in[0];
    const int*   ei     = (const int*)d_in[1];
    const int*   ea     = (const int*)d_in[2];
    const int*   batch  = (const int*)d_in[3];
    const float* rf     = (const float*)d_in[4];
    const float* aemb   = (const float*)d_in[5];
    const float* bemb   = (const float*)d_in[6];
    const float* convw  = (const float*)d_in[7];
    const float* convb  = (const float*)d_in[8];
    const float* ts     = (const float*)d_in[9];
    const float* gammas = (const float*)d_in[10];
    const float* betas  = (const float*)d_in[11];
    const float* fw     = (const float*)d_in[12];
    const float* fb     = (const float*)d_in[13];
    const float* beta   = (const float*)d_in[14];
    float* out = (float*)d_out;

    int N = in_sizes[0] / 9;
    int E = in_sizes[1] / 2;
    int G = in_sizes[4];
    int L = in_sizes[9];

    cudaFuncSetAttribute(k_gemm, cudaFuncAttributeMaxDynamicSharedMemorySize, GEMM_SMEM);

    // encoders + CSR build
    k_convW<<<(L * 16384 + 255) / 256, 256>>>(convw, L);
    k_h0<<<2048, 128>>>(x, aemb, N);
    k_zero_prep<<<256, 256>>>(N);
    k_hist<<<(E + 255) / 256, 256>>>(ei, E);
    int nb = (N + 1023) / 1024;
    k_scan1<<<nb, 1024>>>(N);
    k_scan2<<<1, 256>>>(nb);
    k_scan3<<<nb, 1024>>>(N, E);
    k_scatter<<<(E + 255) / 256, 256>>>(ei, E);
    k_eembed<<<4096, 128>>>(ea, bemb, E);

    int agg_grid = (N + 3) / 4;
    int gemm_grid = (N + 127) / 128;

    // layer 0 (no BN on input)
    k_agg<<<agg_grid, 128>>>(ts, 0, 0, N);
    k_gemm<<<gemm_grid, 256, GEMM_SMEM>>>(convb, 0, 0, N);

    for (int l = 1; l < L; l++) {
        k_bnzero<<<1, 128>>>();
        k_bnstats<<<296, 128>>>(N);
        k_bnfinal<<<1, 128>>>(gammas, betas, l - 1, N);
        k_agg<<<agg_grid, 128>>>(ts, l, 1, N);
        k_gemm<<<gemm_grid, 256, GEMM_SMEM>>>(convb, l, 1, N);
    }

    // final BN + pooling + head
    k_bnzero<<<1, 128>>>();
    k_bnstats<<<296, 128>>>(N);
    k_bnfinal<<<1, 128>>>(gammas, betas, L - 1, N);
    k_poolzero<<<(G * 128 + 255) / 256, 256>>>(G);
    int P = 256;
    int nlen = (N + P - 1) / P;
    k_pool<<<P, 128>>>(batch, N, nlen);
    k_final<<<(G + 3) / 4, 128>>>(fw, fb, beta, rf, out, G);
}

// round 4
// speedup vs baseline: 1.0195x; 1.0195x over previous
#include <cuda_runtime.h>
#include <cuda_bf16.h>
#include <cstdint>

#define MAXN 131072
#define MAXE 655360
#define GMAX 1024

// ---------------- static scratch (no allocations allowed) ----------------
__device__ float          g_h[(size_t)MAXN * 128];        // residual stream (fp32)
__device__ __nv_bfloat16  g_h2[(size_t)MAXN * 128];       // relu(BN(h)) for gather (bf16)
__device__ __nv_bfloat16  g_t[(size_t)MAXN * 128];        // GEMM A operand (bf16)
__device__ __nv_bfloat16  g_esort[(size_t)MAXE * 128];    // bond embeds, CSR order, bf16
__device__ int            g_srcs[MAXE];
__device__ int            g_eid[MAXE];
__device__ int            g_rowptr[MAXN + 1];
__device__ int            g_deg[MAXN];
__device__ int            g_incl[MAXN];
__device__ int            g_cursor[MAXN];
__device__ int            g_bsum[256];
__device__ __nv_bfloat16  g_Wt[8 * 128 * 128];            // Wt[l][n][k] = W[l][k][n], bf16
__device__ float          g_bnsum[128];
__device__ float          g_bnsq[128];
__device__ float          g_bnscale[128];
__device__ float          g_bnshift[128];
__device__ float          g_acc[(size_t)GMAX * 128];
__device__ int            g_cnt[GMAX];

// ---------------- helpers ----------------
__device__ __forceinline__ uint32_t smem_u32(const void* p) {
    uint32_t a;
    asm("{ .reg .u64 t; cvta.to.shared.u64 t, %1; cvt.u32.u64 %0, t; }" : "=r"(a) : "l"(p));
    return a;
}

#define LDMATRIX_X4(r0, r1, r2, r3, addr) \
    asm volatile("ldmatrix.sync.aligned.m8n8.x4.shared.b16 {%0,%1,%2,%3}, [%4];" \
                 : "=r"(r0), "=r"(r1), "=r"(r2), "=r"(r3) : "r"(addr))

#define MMA_BF16(c, a0, a1, a2, a3, b0, b1) \
    asm volatile("mma.sync.aligned.m16n8k16.row.col.f32.bf16.bf16.f32 " \
                 "{%0,%1,%2,%3}, {%4,%5,%6,%7}, {%8,%9}, {%0,%1,%2,%3};" \
                 : "+f"((c)[0]), "+f"((c)[1]), "+f"((c)[2]), "+f"((c)[3]) \
                 : "r"(a0), "r"(a1), "r"(a2), "r"(a3), "r"(b0), "r"(b1))

// ---------------- encoders + CSR ----------------
__global__ void k_h0(const int* __restrict__ x, const float* __restrict__ aemb, int N) {
    int c = threadIdx.x;
    for (int n = blockIdx.x; n < N; n += gridDim.x) {
        float s = 0.f;
#pragma unroll
        for (int f = 0; f < 9; f++) {
            int xi = __ldg(x + n * 9 + f);
            s += __ldg(aemb + ((size_t)f * 64 + xi) * 128 + c);
        }
        g_h[(size_t)n * 128 + c] = s;
    }
}

__global__ void k_zero_prep(int N) {
    for (int i = blockIdx.x * blockDim.x + threadIdx.x; i < N; i += gridDim.x * blockDim.x) {
        g_deg[i] = 0;
        g_cursor[i] = 0;
    }
}

__global__ void k_hist(const int* __restrict__ ei, int E) {
    int e = blockIdx.x * blockDim.x + threadIdx.x;
    if (e < E) atomicAdd(g_deg + ei[E + e], 1);
}

__global__ void k_scan1(int N) {
    __shared__ int sm[1024];
    int i = blockIdx.x * 1024 + threadIdx.x;
    int v = (i < N) ? g_deg[i] : 0;
    sm[threadIdx.x] = v;
    __syncthreads();
    for (int off = 1; off < 1024; off <<= 1) {
        int t = (threadIdx.x >= off) ? sm[threadIdx.x - off] : 0;
        __syncthreads();
        if (threadIdx.x >= off) sm[threadIdx.x] += t;
        __syncthreads();
    }
    if (i < N) g_incl[i] = sm[threadIdx.x];
    if (threadIdx.x == 1023) g_bsum[blockIdx.x] = sm[1023];
}

__global__ void k_scan2(int nb) {
    __shared__ int sm[256];
    int t = threadIdx.x;
    int v = (t < nb) ? g_bsum[t] : 0;
    sm[t] = v;
    __syncthreads();
    for (int off = 1; off < 256; off <<= 1) {
        int u = (t >= off) ? sm[t - off] : 0;
        __syncthreads();
        if (t >= off) sm[t] += u;
        __syncthreads();
    }
    if (t < nb) g_bsum[t] = sm[t] - v;  // exclusive block offsets
}

__global__ void k_scan3(int N, int E) {
    int i = blockIdx.x * 1024 + threadIdx.x;
    if (i < N) g_rowptr[i] = g_incl[i] - g_deg[i] + g_bsum[blockIdx.x];
    if (i == 0) g_rowptr[N] = E;
}

__global__ void k_scatter(const int* __restrict__ ei, int E) {
    int e = blockIdx.x * blockDim.x + threadIdx.x;
    if (e >= E) return;
    int d = ei[E + e];
    int pos = g_rowptr[d] + atomicAdd(g_cursor + d, 1);
    g_srcs[pos] = ei[e];
    g_eid[pos] = e;
}

__global__ void k_eembed(const int* __restrict__ ea, const float* __restrict__ bemb, int E) {
    int c = threadIdx.x;
    for (int p = blockIdx.x; p < E; p += gridDim.x) {
        int e = g_eid[p];
        float s = 0.f;
#pragma unroll
        for (int f = 0; f < 3; f++) {
            int ai = __ldg(ea + e * 3 + f);
            s += __ldg(bemb + ((size_t)f * 8 + ai) * 128 + c);
        }
        // streaming store: keep this out of L2's way
        __stcs((__nv_bfloat16*)(g_esort + (size_t)p * 128 + c), __float2bfloat16(s));
    }
}

__global__ void k_convW(const float* __restrict__ w, int L) {
    int i = blockIdx.x * blockDim.x + threadIdx.x;
    int tot = L * 16384;
    if (i < tot) {
        int l = i >> 14, r = i & 16383, n = r >> 7, k = r & 127;
        g_Wt[i] = __float2bfloat16(w[(l << 14) + (k << 7) + n]);  // Wt[l][n][k] = W[l][k][n]
    }
}

// ---------------- BatchNorm stats ----------------
__global__ void k_bnzero() {
    int c = threadIdx.x;
    g_bnsum[c] = 0.f;
    g_bnsq[c] = 0.f;
}

__global__ void k_bnstats(int N) {
    int c = threadIdx.x;
    float s = 0.f, q = 0.f;
    for (int n = blockIdx.x; n < N; n += gridDim.x) {
        float v = g_h[(size_t)n * 128 + c];
        s += v;
        q = fmaf(v, v, q);
    }
    atomicAdd(g_bnsum + c, s);
    atomicAdd(g_bnsq + c, q);
}

__global__ void k_bnfinal(const float* __restrict__ gammas, const float* __restrict__ betas,
                          int l, int N) {
    int c = threadIdx.x;
    float invN = 1.f / (float)N;
    float mu = g_bnsum[c] * invN;
    float var = g_bnsq[c] * invN - mu * mu;
    float inv = rsqrtf(var + 1e-5f);
    float scv = inv * gammas[l * 128 + c];
    g_bnscale[c] = scv;
    g_bnshift[c] = betas[l * 128 + c] - mu * scv;
}

// ---------------- h2 = bf16(relu(BN(h))) (or bf16(h) for layer 0) ----------------
__global__ void k_prep(int use_bn, int N) {
    int idx = blockIdx.x * blockDim.x + threadIdx.x;   // over N*64 channel pairs
    if (idx >= N * 64) return;
    int row = idx >> 6, cp = (idx & 63) << 1;
    float2 v = *(const float2*)(g_h + (size_t)row * 128 + cp);
    if (use_bn) {
        float2 sc = *(const float2*)(g_bnscale + cp);
        float2 sh = *(const float2*)(g_bnshift + cp);
        v.x = fmaxf(fmaf(v.x, sc.x, sh.x), 0.f);
        v.y = fmaxf(fmaf(v.y, sc.y, sh.y), 0.f);
    }
    __nv_bfloat162 b = __floats2bfloat162_rn(v.x, v.y);
    *(__nv_bfloat162*)(g_h2 + (size_t)row * 128 + cp) = b;
}

// ---------------- softmax aggregation (warp per node, branchless 1-exp) -------
__device__ __forceinline__ void smupd(float& m, float& s, float& w, float msg, float tt) {
    float lg = msg * tt;
    float mn = fmaxf(m, lg);
    float e = __expf(fminf(m, lg) - mn);
    bool gt = lg > m;
    float sA = fmaf(s, e, 1.f);
    float sB = s + e;
    float wA = fmaf(w, e, msg);
    float wB = fmaf(e, msg, w);
    s = gt ? sA : sB;
    w = gt ? wA : wB;
    m = mn;
}

__global__ void __launch_bounds__(128) k_agg(const float* __restrict__ ts, int l, int N) {
    int gw = (blockIdx.x << 2) + (threadIdx.x >> 5);
    if (gw >= N) return;
    int lane = threadIdx.x & 31;
    int c0 = lane << 2;
    float tt = __ldg(ts + l);

    // hin = h2 row of dst
    uint2 hu = *(const uint2*)(g_h2 + (size_t)gw * 128 + c0);
    float2 hi01 = __bfloat1622float2(*reinterpret_cast<__nv_bfloat162*>(&hu.x));
    float2 hi23 = __bfloat1622float2(*reinterpret_cast<__nv_bfloat162*>(&hu.y));

    int p0 = __ldg(g_rowptr + gw), p1 = __ldg(g_rowptr + gw + 1);
    float m0 = -3.0e38f, m1 = -3.0e38f, m2 = -3.0e38f, m3 = -3.0e38f;
    float s0 = 0.f, s1 = 0.f, s2 = 0.f, s3 = 0.f;
    float w0 = 0.f, w1 = 0.f, w2 = 0.f, w3 = 0.f;

    int p = p0;
    int si = (p < p1) ? __ldg(g_srcs + p) : 0;
    while (p < p1) {
        int cur = si;
        int pn = p + 1;
        si = (pn < p1) ? __ldg(g_srcs + pn) : 0;

        uint2 su = *(const uint2*)(g_h2 + (size_t)cur * 128 + c0);
        uint2 eu = __ldcs((const uint2*)(g_esort + (size_t)p * 128 + c0));
        float2 s01 = __bfloat1622float2(*reinterpret_cast<__nv_bfloat162*>(&su.x));
        float2 s23 = __bfloat1622float2(*reinterpret_cast<__nv_bfloat162*>(&su.y));
        float2 e01 = __bfloat1622float2(*reinterpret_cast<__nv_bfloat162*>(&eu.x));
        float2 e23 = __bfloat1622float2(*reinterpret_cast<__nv_bfloat162*>(&eu.y));

        float q0 = fmaxf(s01.x + e01.x, 0.f) + 1e-7f;
        float q1 = fmaxf(s01.y + e01.y, 0.f) + 1e-7f;
        float q2 = fmaxf(s23.x + e23.x, 0.f) + 1e-7f;
        float q3 = fmaxf(s23.y + e23.y, 0.f) + 1e-7f;
        smupd(m0, s0, w0, q0, tt);
        smupd(m1, s1, w1, q1, tt);
        smupd(m2, s2, w2, q2, tt);
        smupd(m3, s3, w3, q3, tt);
        p = pn;
    }

    float o0 = hi01.x + w0 / (s0 + 1e-16f);
    float o1 = hi01.y + w1 / (s1 + 1e-16f);
    float o2 = hi23.x + w2 / (s2 + 1e-16f);
    float o3 = hi23.y + w3 / (s3 + 1e-16f);

    __nv_bfloat162 t01 = __floats2bfloat162_rn(o0, o1);
    __nv_bfloat162 t23 = __floats2bfloat162_rn(o2, o3);
    uint2 st;
    st.x = *reinterpret_cast<uint32_t*>(&t01);
    st.y = *reinterpret_cast<uint32_t*>(&t23);
    *(uint2*)(g_t + (size_t)gw * 128 + c0) = st;
}

// ---------------- mma.sync GEMM: h_new = t @ W^T (+b) (+h_old) ----------------
#define GEMM_SMEM (2 * 128 * 272)

__global__ void __launch_bounds__(256) k_gemm(const float* __restrict__ conv_b,
                                              int l, int add_res, int N) {
    extern __shared__ char smem[];
    char* sA = smem;
    char* sB = smem + 128 * 272;
    int tid = threadIdx.x;
    int node0 = blockIdx.x * 128;

    const uint4* asrc = (const uint4*)(g_t + (size_t)node0 * 128);
    const uint4* bsrc = (const uint4*)(g_Wt + (size_t)l * 16384);
#pragma unroll
    for (int i = tid; i < 2048; i += 256) {
        int row = i >> 4, cq = i & 15;
        *(uint4*)(sA + row * 272 + cq * 16) = asrc[i];
        *(uint4*)(sB + row * 272 + cq * 16) = bsrc[i];
    }
    __syncthreads();

    int wid = tid >> 5, lane = tid & 31;
    int wm = wid >> 1, wn = wid & 1;           // 4 x 2 warp grid
    uint32_t sab = smem_u32(sA), sbb = smem_u32(sB);

    float acc[2][8][4];
#pragma unroll
    for (int mt = 0; mt < 2; mt++)
#pragma unroll
        for (int nt = 0; nt < 8; nt++)
#pragma unroll
            for (int q = 0; q < 4; q++) acc[mt][nt][q] = 0.f;

    int lrow = lane & 15, lhalf = (lane >> 4) << 3;

#pragma unroll
    for (int ks = 0; ks < 8; ks++) {
        int k0 = ks * 16;
        uint32_t a[2][4];
#pragma unroll
        for (int mt = 0; mt < 2; mt++) {
            int r = wm * 32 + mt * 16 + lrow;
            uint32_t addr = sab + r * 272 + (k0 + lhalf) * 2;
            LDMATRIX_X4(a[mt][0], a[mt][1], a[mt][2], a[mt][3], addr);
        }
        uint32_t b[4][4];
#pragma unroll
        for (int nq = 0; nq < 4; nq++) {
            int nr = wn * 64 + nq * 16 + lrow;
            uint32_t addr = sbb + nr * 272 + (k0 + lhalf) * 2;
            LDMATRIX_X4(b[nq][0], b[nq][1], b[nq][2], b[nq][3], addr);
        }
#pragma unroll
        for (int mt = 0; mt < 2; mt++)
#pragma unroll
            for (int nq = 0; nq < 4; nq++) {
                MMA_BF16(acc[mt][nq * 2 + 0], a[mt][0], a[mt][1], a[mt][2], a[mt][3],
                         b[nq][0], b[nq][2]);
                MMA_BF16(acc[mt][nq * 2 + 1], a[mt][0], a[mt][1], a[mt][2], a[mt][3],
                         b[nq][1], b[nq][3]);
            }
    }

    // epilogue: bias (+ residual), write fp32 h
    int qrow = lane >> 2, qcol = (lane & 3) * 2;
#pragma unroll
    for (int mt = 0; mt < 2; mt++) {
#pragma unroll
        for (int nt = 0; nt < 8; nt++) {
            int col = wn * 64 + nt * 8 + qcol;
            float2 bv = *(const float2*)(conv_b + l * 128 + col);
            int row0 = node0 + wm * 32 + mt * 16 + qrow;
#pragma unroll
            for (int hh = 0; hh < 2; hh++) {
                int row = row0 + hh * 8;
                if (row < N) {
                    float* dst = g_h + (size_t)row * 128 + col;
                    float vx = acc[mt][nt][hh * 2 + 0] + bv.x;
                    float vy = acc[mt][nt][hh * 2 + 1] + bv.y;
                    if (add_res) {
                        float2 r = *(const float2*)dst;
                        vx += r.x; vy += r.y;
                    }
                    float2 o; o.x = vx; o.y = vy;
                    *(float2*)dst = o;
                }
            }
        }
    }
}

// ---------------- pooling + head ----------------
__global__ void k_poolzero(int G) {
    int i = blockIdx.x * blockDim.x + threadIdx.x;
    if (i < G * 128) g_acc[i] = 0.f;
    if (i < G) g_cnt[i] = 0;
}

__global__ void k_pool(const int* __restrict__ batch, int N, int nlen) {
    int c = threadIdx.x;
    int n0 = blockIdx.x * nlen, n1 = min(N, n0 + nlen);
    if (n0 >= n1) return;
    float sc = g_bnscale[c], sh = g_bnshift[c];
    int cur = __ldg(batch + n0);
    float acc = 0.f;
    int cnt = 0;
    for (int n = n0; n < n1; n++) {
        int gg = __ldg(batch + n);
        if (gg != cur) {
            atomicAdd(g_acc + (size_t)cur * 128 + c, acc);
            if (c == 0) atomicAdd(g_cnt + cur, cnt);
            acc = 0.f; cnt = 0; cur = gg;
        }
        float v = fmaxf(fmaf(g_h[(size_t)n * 128 + c], sc, sh), 0.f);
        acc += v;
        cnt++;
    }
    atomicAdd(g_acc + (size_t)cur * 128 + c, acc);
    if (c == 0) atomicAdd(g_cnt + cur, cnt);
}

__global__ void k_final(const float* __restrict__ fw, const float* __restrict__ fb,
                        const float* __restrict__ beta, const float* __restrict__ rf,
                        float* __restrict__ out, int G) {
    int wid = threadIdx.x >> 5, lane = threadIdx.x & 31;
    int g = blockIdx.x * 4 + wid;
    if (g >= G) return;
    float4 a = ((const float4*)(g_acc + (size_t)g * 128))[lane];
    float4 w = ((const float4*)fw)[lane];
    float dot = a.x * w.x + a.y * w.y + a.z * w.z + a.w * w.w;
#pragma unroll
    for (int o = 16; o > 0; o >>= 1) dot += __shfl_down_sync(0xFFFFFFFFu, dot, o);
    if (lane == 0) {
        float cntf = fmaxf((float)g_cnt[g], 1.f);
        float pred = dot / cntf + fb[0];
        float sg = 1.f / (1.f + __expf(-pred));
        float b = beta[0];
        out[g] = (1.f - b) * sg + b * rf[g];
    }
}

// ---------------- launch ----------------
extern "C" void kernel_launch(void* const* d_in, const int* in_sizes, int n_in,
                              void* d_out, int out_size) {
    const int*   x      = (const int*)d_in[0];
    const int*   ei     = (const int*)d_in[1];
    const int*   ea     = (const int*)d_in[2];
    const int*   batch  = (const int*)d_in[3];
    const float* rf     = (const float*)d_in[4];
    const float* aemb   = (const float*)d_in[5];
    const float* bemb   = (const float*)d_in[6];
    const float* convw  = (const float*)d_in[7];
    const float* convb  = (const float*)d_in[8];
    const float* ts     = (const float*)d_in[9];
    const float* gammas = (const float*)d_in[10];
    const float* betas  = (const float*)d_in[11];
    const float* fw     = (const float*)d_in[12];
    const float* fb     = (const float*)d_in[13];
    const float* beta   = (const float*)d_in[14];
    float* out = (float*)d_out;

    int N = in_sizes[0] / 9;
    int E = in_sizes[1] / 2;
    int G = in_sizes[4];
    int L = in_sizes[9];

    cudaFuncSetAttribute(k_gemm, cudaFuncAttributeMaxDynamicSharedMemorySize, GEMM_SMEM);

    // encoders + CSR build
    k_convW<<<(L * 16384 + 255) / 256, 256>>>(convw, L);
    k_h0<<<2048, 128>>>(x, aemb, N);
    k_zero_prep<<<256, 256>>>(N);
    k_hist<<<(E + 255) / 256, 256>>>(ei, E);
    int nb = (N + 1023) / 1024;
    k_scan1<<<nb, 1024>>>(N);
    k_scan2<<<1, 256>>>(nb);
    k_scan3<<<nb, 1024>>>(N, E);
    k_scatter<<<(E + 255) / 256, 256>>>(ei, E);
    k_eembed<<<4096, 128>>>(ea, bemb, E);

    int agg_grid = (N + 3) / 4;
    int gemm_grid = (N + 127) / 128;
    int prep_grid = (N * 64 + 255) / 256;

    // layer 0 (no BN on input)
    k_prep<<<prep_grid, 256>>>(0, N);
    k_agg<<<agg_grid, 128>>>(ts, 0, N);
    k_gemm<<<gemm_grid, 256, GEMM_SMEM>>>(convb, 0, 0, N);

    for (int l = 1; l < L; l++) {
        k_bnzero<<<1, 128>>>();
        k_bnstats<<<296, 128>>>(N);
        k_bnfinal<<<1, 128>>>(gammas, betas, l - 1, N);
        k_prep<<<prep_grid, 256>>>(1, N);
        k_agg<<<agg_grid, 128>>>(ts, l, N);
        k_gemm<<<gemm_grid, 256, GEMM_SMEM>>>(convb, l, 1, N);
    }

    // final BN + pooling + head
    k_bnzero<<<1, 128>>>();
    k_bnstats<<<296, 128>>>(N);
    k_bnfinal<<<1, 128>>>(gammas, betas, L - 1, N);
    k_poolzero<<<(G * 128 + 255) / 256, 256>>>(G);
    int P = 256;
    int nlen = (N + P - 1) / P;
    k_pool<<<P, 128>>>(batch, N, nlen);
    k_final<<<(G + 3) / 4, 128>>>(fw, fb, beta, rf, out, G);
}

// round 5
// speedup vs baseline: 1.8104x; 1.7758x over previous
#include <cuda_runtime.h>
#include <cuda_bf16.h>
#include <cstdint>

#define MAXN 131072
#define MAXE 655360
#define GMAX 1024

// ---------------- static scratch (zero-initialized at module load) ----------------
__device__ float          g_h[(size_t)MAXN * 128];        // residual stream (fp32)
__device__ __nv_bfloat16  g_h2[(size_t)MAXN * 128];       // relu(BN(h)) for gather (bf16)
__device__ __nv_bfloat16  g_t[(size_t)MAXN * 128];        // GEMM A operand (bf16)
__device__ __nv_bfloat16  g_ecomb[512 * 128];             // combined bond-emb table (bf16)
__device__ int            g_srcs[MAXE];                   // src node, CSR(dst) order
__device__ int            g_eattr[MAXE];                  // packed combo idx, CSR order
__device__ int            g_rowptr[MAXN + 1];
__device__ int            g_deg[MAXN];                    // zeroed by cleanup
__device__ int            g_cursor[MAXN];                 // zeroed by cleanup
__device__ __nv_bfloat16  g_Wt[8 * 128 * 128];            // Wt[l][n][k] = W[l][k][n]
__device__ float          g_bnsum[8 * 128];               // per-layer stats (cleanup-zeroed)
__device__ float          g_bnsq[8 * 128];
__device__ float          g_acc[(size_t)GMAX * 128];      // pooling accum (cleanup-zeroed)
__device__ int            g_cnt[GMAX];

// ---------------- helpers ----------------
__device__ __forceinline__ uint32_t smem_u32(const void* p) {
    uint32_t a;
    asm("{ .reg .u64 t; cvta.to.shared.u64 t, %1; cvt.u32.u64 %0, t; }" : "=r"(a) : "l"(p));
    return a;
}

#define LDMATRIX_X4(r0, r1, r2, r3, addr) \
    asm volatile("ldmatrix.sync.aligned.m8n8.x4.shared.b16 {%0,%1,%2,%3}, [%4];" \
                 : "=r"(r0), "=r"(r1), "=r"(r2), "=r"(r3) : "r"(addr))

#define MMA_BF16(c, a0, a1, a2, a3, b0, b1) \
    asm volatile("mma.sync.aligned.m16n8k16.row.col.f32.bf16.bf16.f32 " \
                 "{%0,%1,%2,%3}, {%4,%5,%6,%7}, {%8,%9}, {%0,%1,%2,%3};" \
                 : "+f"((c)[0]), "+f"((c)[1]), "+f"((c)[2]), "+f"((c)[3]) \
                 : "r"(a0), "r"(a1), "r"(a2), "r"(a3), "r"(b0), "r"(b1))

// ---------------- fused init: convW + combined bond table + h0 + degree hist --------
// block ranges: [0, L*128) convW | [.., +512) ecomb | [.., +2048) h0 | [.., +2048) hist
__global__ void __launch_bounds__(128) k_init(const int* __restrict__ x,
                                              const float* __restrict__ aemb,
                                              const float* __restrict__ bemb,
                                              const float* __restrict__ w,
                                              const int* __restrict__ ei,
                                              int N, int E, int L) {
    int b = blockIdx.x;
    int tid = threadIdx.x;
    int gcw = L * 128;
    if (b < gcw) {                       // transpose conv weights -> bf16
        int i = b * 128 + tid;
        int l = i >> 14, r = i & 16383, n = r >> 7, k = r & 127;
        g_Wt[i] = __float2bfloat16(w[(l << 14) + (k << 7) + n]);
        return;
    }
    b -= gcw;
    if (b < 512) {                       // combined bond-embedding table
        int a0 = b & 7, a1 = (b >> 3) & 7, a2 = (b >> 6) & 7;
        float s = __ldg(bemb + (0 * 8 + a0) * 128 + tid)
                + __ldg(bemb + (1 * 8 + a1) * 128 + tid)
                + __ldg(bemb + (2 * 8 + a2) * 128 + tid);
        g_ecomb[b * 128 + tid] = __float2bfloat16(s);
        return;
    }
    b -= 512;
    if (b < 2048) {                      // atom encoder -> h (fp32) and h2 (bf16)
        for (int n = b; n < N; n += 2048) {
            float s = 0.f;
#pragma unroll
            for (int f = 0; f < 9; f++) {
                int xi = __ldg(x + n * 9 + f);
                s += __ldg(aemb + ((size_t)f * 64 + xi) * 128 + tid);
            }
            g_h[(size_t)n * 128 + tid] = s;
            g_h2[(size_t)n * 128 + tid] = __float2bfloat16(s);
        }
        return;
    }
    b -= 2048;
    // degree histogram (g_deg starts zeroed; re-zeroed by k_cleanup)
    for (int e = b * 128 + tid; e < E; e += 2048 * 128)
        atomicAdd(g_deg + __ldg(ei + E + e), 1);
}

// ---------------- single-kernel exclusive scan over degrees ----------------
__global__ void __launch_bounds__(1024) k_scan(int N, int E) {
    __shared__ int warp_tot[32];
    int tid = threadIdx.x, lane = tid & 31, wid = tid >> 5;
    int run = 0;
    for (int t0 = 0; t0 < N; t0 += 1024) {
        int i = t0 + tid;
        int v = (i < N) ? g_deg[i] : 0;
        int xv = v;
#pragma unroll
        for (int o = 1; o < 32; o <<= 1) {
            int y = __shfl_up_sync(0xFFFFFFFFu, xv, o);
            if (lane >= o) xv += y;
        }
        if (lane == 31) warp_tot[wid] = xv;
        __syncthreads();
        if (wid == 0) {
            int wv = warp_tot[lane];
#pragma unroll
            for (int o = 1; o < 32; o <<= 1) {
                int y = __shfl_up_sync(0xFFFFFFFFu, wv, o);
                if (lane >= o) wv += y;
            }
            warp_tot[lane] = wv;
        }
        __syncthreads();
        int woff = (wid > 0) ? warp_tot[wid - 1] : 0;
        if (i < N) g_rowptr[i] = run + woff + xv - v;   // exclusive
        run += warp_tot[31];
        __syncthreads();
    }
    if (tid == 0) g_rowptr[N] = E;
}

// ---------------- scatter edges into CSR order + pack attributes ----------------
__global__ void k_scatter(const int* __restrict__ ei, const int* __restrict__ ea, int E) {
    int e = blockIdx.x * blockDim.x + threadIdx.x;
    if (e >= E) return;
    int d = __ldg(ei + E + e);
    int pos = g_rowptr[d] + atomicAdd(g_cursor + d, 1);
    g_srcs[pos] = __ldg(ei + e);
    int a0 = __ldg(ea + e * 3 + 0), a1 = __ldg(ea + e * 3 + 1), a2 = __ldg(ea + e * 3 + 2);
    g_eattr[pos] = a0 + a1 * 8 + a2 * 64;
}

// ---------------- softmax aggregation (warp/node, no-max softmax, 2x unroll) -------
__device__ __forceinline__ void aggproc(const uint2& su, const uint2& eu, float tt,
                                        float& s0, float& s1, float& s2, float& s3,
                                        float& w0, float& w1, float& w2, float& w3) {
    float2 h01 = __bfloat1622float2(*reinterpret_cast<const __nv_bfloat162*>(&su.x));
    float2 h23 = __bfloat1622float2(*reinterpret_cast<const __nv_bfloat162*>(&su.y));
    float2 e01 = __bfloat1622float2(*reinterpret_cast<const __nv_bfloat162*>(&eu.x));
    float2 e23 = __bfloat1622float2(*reinterpret_cast<const __nv_bfloat162*>(&eu.y));
    float q0 = fmaxf(h01.x + e01.x, 0.f) + 1e-7f;
    float q1 = fmaxf(h01.y + e01.y, 0.f) + 1e-7f;
    float q2 = fmaxf(h23.x + e23.x, 0.f) + 1e-7f;
    float q3 = fmaxf(h23.y + e23.y, 0.f) + 1e-7f;
    float x0 = __expf(q0 * tt), x1 = __expf(q1 * tt);
    float x2 = __expf(q2 * tt), x3 = __expf(q3 * tt);
    s0 += x0; s1 += x1; s2 += x2; s3 += x3;
    w0 = fmaf(x0, q0, w0); w1 = fmaf(x1, q1, w1);
    w2 = fmaf(x2, q2, w2); w3 = fmaf(x3, q3, w3);
}

__global__ void __launch_bounds__(128) k_agg(const float* __restrict__ ts, int l, int N) {
    int gw = (blockIdx.x << 2) + (threadIdx.x >> 5);
    if (gw >= N) return;
    int lane = threadIdx.x & 31;
    int c0 = lane << 2;
    float tt = __ldg(ts + l);

    uint2 hu = *(const uint2*)(g_h2 + (size_t)gw * 128 + c0);
    float2 hi01 = __bfloat1622float2(*reinterpret_cast<__nv_bfloat162*>(&hu.x));
    float2 hi23 = __bfloat1622float2(*reinterpret_cast<__nv_bfloat162*>(&hu.y));

    int p0 = __ldg(g_rowptr + gw), p1 = __ldg(g_rowptr + gw + 1);
    float s0 = 0.f, s1 = 0.f, s2 = 0.f, s3 = 0.f;
    float w0 = 0.f, w1 = 0.f, w2 = 0.f, w3 = 0.f;

    int p = p0;
    while (p + 2 <= p1) {
        int siA = __ldg(g_srcs + p),     cbA = __ldg(g_eattr + p);
        int siB = __ldg(g_srcs + p + 1), cbB = __ldg(g_eattr + p + 1);
        uint2 suA = *(const uint2*)(g_h2 + (size_t)siA * 128 + c0);
        uint2 euA = *(const uint2*)(g_ecomb + (size_t)cbA * 128 + c0);
        uint2 suB = *(const uint2*)(g_h2 + (size_t)siB * 128 + c0);
        uint2 euB = *(const uint2*)(g_ecomb + (size_t)cbB * 128 + c0);
        aggproc(suA, euA, tt, s0, s1, s2, s3, w0, w1, w2, w3);
        aggproc(suB, euB, tt, s0, s1, s2, s3, w0, w1, w2, w3);
        p += 2;
    }
    if (p < p1) {
        int si = __ldg(g_srcs + p), cb = __ldg(g_eattr + p);
        uint2 su = *(const uint2*)(g_h2 + (size_t)si * 128 + c0);
        uint2 eu = *(const uint2*)(g_ecomb + (size_t)cb * 128 + c0);
        aggproc(su, eu, tt, s0, s1, s2, s3, w0, w1, w2, w3);
    }

    float o0 = hi01.x + w0 / (s0 + 1e-16f);
    float o1 = hi01.y + w1 / (s1 + 1e-16f);
    float o2 = hi23.x + w2 / (s2 + 1e-16f);
    float o3 = hi23.y + w3 / (s3 + 1e-16f);

    __nv_bfloat162 t01 = __floats2bfloat162_rn(o0, o1);
    __nv_bfloat162 t23 = __floats2bfloat162_rn(o2, o3);
    uint2 st;
    st.x = *reinterpret_cast<uint32_t*>(&t01);
    st.y = *reinterpret_cast<uint32_t*>(&t23);
    *(uint2*)(g_t + (size_t)gw * 128 + c0) = st;
}

// ---------------- mma.sync GEMM + fused BN stats ----------------
#define GEMM_SMEM (2 * 128 * 272 + 1024)

__global__ void __launch_bounds__(256) k_gemm(const float* __restrict__ conv_b,
                                              int l, int add_res, int N) {
    extern __shared__ char smem[];
    char* sA = smem;
    char* sB = smem + 128 * 272;
    float* sbn = (float*)(smem + 2 * 128 * 272);   // [256]: sums | sumsq
    int tid = threadIdx.x;
    int node0 = blockIdx.x * 128;

    if (tid < 256) sbn[tid] = 0.f;

    const uint4* asrc = (const uint4*)(g_t + (size_t)node0 * 128);
    const uint4* bsrc = (const uint4*)(g_Wt + (size_t)l * 16384);
#pragma unroll
    for (int i = tid; i < 2048; i += 256) {
        int row = i >> 4, cq = i & 15;
        *(uint4*)(sA + row * 272 + cq * 16) = asrc[i];
        *(uint4*)(sB + row * 272 + cq * 16) = bsrc[i];
    }
    __syncthreads();

    int wid = tid >> 5, lane = tid & 31;
    int wm = wid >> 1, wn = wid & 1;           // 4 x 2 warp grid
    uint32_t sab = smem_u32(sA), sbb = smem_u32(sB);

    float acc[2][8][4];
#pragma unroll
    for (int mt = 0; mt < 2; mt++)
#pragma unroll
        for (int nt = 0; nt < 8; nt++)
#pragma unroll
            for (int q = 0; q < 4; q++) acc[mt][nt][q] = 0.f;

    int lrow = lane & 15, lhalf = (lane >> 4) << 3;

#pragma unroll
    for (int ks = 0; ks < 8; ks++) {
        int k0 = ks * 16;
        uint32_t a[2][4];
#pragma unroll
        for (int mt = 0; mt < 2; mt++) {
            int r = wm * 32 + mt * 16 + lrow;
            uint32_t addr = sab + r * 272 + (k0 + lhalf) * 2;
            LDMATRIX_X4(a[mt][0], a[mt][1], a[mt][2], a[mt][3], addr);
        }
        uint32_t bq[4][4];
#pragma unroll
        for (int nq = 0; nq < 4; nq++) {
            int nr = wn * 64 + nq * 16 + lrow;
            uint32_t addr = sbb + nr * 272 + (k0 + lhalf) * 2;
            LDMATRIX_X4(bq[nq][0], bq[nq][1], bq[nq][2], bq[nq][3], addr);
        }
#pragma unroll
        for (int mt = 0; mt < 2; mt++)
#pragma unroll
            for (int nq = 0; nq < 4; nq++) {
                MMA_BF16(acc[mt][nq * 2 + 0], a[mt][0], a[mt][1], a[mt][2], a[mt][3],
                         bq[nq][0], bq[nq][2]);
                MMA_BF16(acc[mt][nq * 2 + 1], a[mt][0], a[mt][1], a[mt][2], a[mt][3],
                         bq[nq][1], bq[nq][3]);
            }
    }

    // epilogue: bias (+residual) -> h, accumulate BN stats
    int qrow = lane >> 2, qcol = (lane & 3) * 2;
    float colS[16], colQ[16];
#pragma unroll
    for (int i = 0; i < 16; i++) { colS[i] = 0.f; colQ[i] = 0.f; }

#pragma unroll
    for (int mt = 0; mt < 2; mt++) {
#pragma unroll
        for (int nt = 0; nt < 8; nt++) {
            int col = wn * 64 + nt * 8 + qcol;
            float2 bv = *(const float2*)(conv_b + l * 128 + col);
            int row0 = node0 + wm * 32 + mt * 16 + qrow;
#pragma unroll
            for (int hh = 0; hh < 2; hh++) {
                int row = row0 + hh * 8;
                if (row < N) {
                    float* dst = g_h + (size_t)row * 128 + col;
                    float vx = acc[mt][nt][hh * 2 + 0] + bv.x;
                    float vy = acc[mt][nt][hh * 2 + 1] + bv.y;
                    if (add_res) {
                        float2 r = *(const float2*)dst;
                        vx += r.x; vy += r.y;
                    }
                    float2 o; o.x = vx; o.y = vy;
                    *(float2*)dst = o;
                    colS[nt * 2 + 0] += vx;
                    colQ[nt * 2 + 0] = fmaf(vx, vx, colQ[nt * 2 + 0]);
                    colS[nt * 2 + 1] += vy;
                    colQ[nt * 2 + 1] = fmaf(vy, vy, colQ[nt * 2 + 1]);
                }
            }
        }
    }

    // reduce over the 8 qrow lanes (strides 4,8,16), then smem atomics
#pragma unroll
    for (int i = 0; i < 16; i++) {
        float vs = colS[i], vq = colQ[i];
        vs += __shfl_xor_sync(0xFFFFFFFFu, vs, 4);
        vs += __shfl_xor_sync(0xFFFFFFFFu, vs, 8);
        vs += __shfl_xor_sync(0xFFFFFFFFu, vs, 16);
        vq += __shfl_xor_sync(0xFFFFFFFFu, vq, 4);
        vq += __shfl_xor_sync(0xFFFFFFFFu, vq, 8);
        vq += __shfl_xor_sync(0xFFFFFFFFu, vq, 16);
        if (lane < 4) {
            int col = wn * 64 + (i >> 1) * 8 + lane * 2 + (i & 1);
            atomicAdd(sbn + col, vs);
            atomicAdd(sbn + 128 + col, vq);
        }
    }
    __syncthreads();
    if (tid < 128) {
        atomicAdd(g_bnsum + l * 128 + tid, sbn[tid]);
        atomicAdd(g_bnsq + l * 128 + tid, sbn[128 + tid]);
    }
}

// ---------------- h2 = bf16(relu(BN(h))) using stats slot l ----------------
__global__ void k_prep(const float* __restrict__ gammas, const float* __restrict__ betas,
                       int l, int N, float invN) {
    int idx = blockIdx.x * blockDim.x + threadIdx.x;   // N*64 channel pairs
    if (idx >= N * 64) return;
    int row = idx >> 6, cp = (idx & 63) << 1;
    float2 sm = *(const float2*)(g_bnsum + l * 128 + cp);
    float2 sq = *(const float2*)(g_bnsq + l * 128 + cp);
    float2 ga = *(const float2*)(gammas + l * 128 + cp);
    float2 be = *(const float2*)(betas + l * 128 + cp);
    float mu0 = sm.x * invN, mu1 = sm.y * invN;
    float va0 = sq.x * invN - mu0 * mu0, va1 = sq.y * invN - mu1 * mu1;
    float sc0 = rsqrtf(va0 + 1e-5f) * ga.x, sc1 = rsqrtf(va1 + 1e-5f) * ga.y;
    float sh0 = be.x - mu0 * sc0, sh1 = be.y - mu1 * sc1;
    float2 v = *(const float2*)(g_h + (size_t)row * 128 + cp);
    v.x = fmaxf(fmaf(v.x, sc0, sh0), 0.f);
    v.y = fmaxf(fmaf(v.y, sc1, sh1), 0.f);
    *(__nv_bfloat162*)(g_h2 + (size_t)row * 128 + cp) = __floats2bfloat162_rn(v.x, v.y);
}

// ---------------- pooling (final BN inline) + head ----------------
__global__ void k_pool(const int* __restrict__ batch, const float* __restrict__ gammas,
                       const float* __restrict__ betas, int l, int N, int nlen, float invN) {
    int c = threadIdx.x;
    int n0 = blockIdx.x * nlen, n1 = min(N, n0 + nlen);
    if (n0 >= n1) return;
    float sm = g_bnsum[l * 128 + c], sq = g_bnsq[l * 128 + c];
    float mu = sm * invN;
    float var = sq * invN - mu * mu;
    float sc = rsqrtf(var + 1e-5f) * __ldg(gammas + l * 128 + c);
    float sh = __ldg(betas + l * 128 + c) - mu * sc;
    int cur = __ldg(batch + n0);
    float acc = 0.f;
    int cnt = 0;
    for (int n = n0; n < n1; n++) {
        int gg = __ldg(batch + n);
        if (gg != cur) {
            atomicAdd(g_acc + (size_t)cur * 128 + c, acc);
            if (c == 0) atomicAdd(g_cnt + cur, cnt);
            acc = 0.f; cnt = 0; cur = gg;
        }
        float v = fmaxf(fmaf(g_h[(size_t)n * 128 + c], sc, sh), 0.f);
        acc += v;
        cnt++;
    }
    atomicAdd(g_acc + (size_t)cur * 128 + c, acc);
    if (c == 0) atomicAdd(g_cnt + cur, cnt);
}

__global__ void k_final(const float* __restrict__ fw, const float* __restrict__ fb,
                        const float* __restrict__ beta, const float* __restrict__ rf,
                        float* __restrict__ out, int G) {
    int wid = threadIdx.x >> 5, lane = threadIdx.x & 31;
    int g = blockIdx.x * 4 + wid;
    if (g >= G) return;
    float4 a = ((const float4*)(g_acc + (size_t)g * 128))[lane];
    float4 w = ((const float4*)fw)[lane];
    float dot = a.x * w.x + a.y * w.y + a.z * w.z + a.w * w.w;
#pragma unroll
    for (int o = 16; o > 0; o >>= 1) dot += __shfl_down_sync(0xFFFFFFFFu, dot, o);
    if (lane == 0) {
        float cntf = fmaxf((float)g_cnt[g], 1.f);
        float pred = dot / cntf + fb[0];
        float sg = 1.f / (1.f + __expf(-pred));
        float b = beta[0];
        out[g] = (1.f - b) * sg + b * rf[g];
    }
}

// ---------------- restore zeroed state for next (graph-replayed) call --------------
__global__ void k_cleanup(int N, int G) {
    int i = blockIdx.x * blockDim.x + threadIdx.x;
    int stride = gridDim.x * blockDim.x;
    for (int j = i; j < N; j += stride) { g_deg[j] = 0; g_cursor[j] = 0; }
    for (int j = i; j < G * 128; j += stride) g_acc[j] = 0.f;
    for (int j = i; j < G; j += stride) g_cnt[j] = 0;
    for (int j = i; j < 1024; j += stride) { g_bnsum[j] = 0.f; g_bnsq[j] = 0.f; }
}

// ---------------- launch ----------------
extern "C" void kernel_launch(void* const* d_in, const int* in_sizes, int n_in,
                              void* d_out, int out_size) {
    const int*   x      = (const int*)d_in[0];
    const int*   ei     = (const int*)d_in[1];
    const int*   ea     = (const int*)d_in[2];
    const int*   batch  = (const int*)d_in[3];
    const float* rf     = (const float*)d_in[4];
    const float* aemb   = (const float*)d_in[5];
    const float* bemb   = (const float*)d_in[6];
    const float* convw  = (const float*)d_in[7];
    const float* convb  = (const float*)d_in[8];
    const float* ts     = (const float*)d_in[9];
    const float* gammas = (const float*)d_in[10];
    const float* betas  = (const float*)d_in[11];
    const float* fw     = (const float*)d_in[12];
    const float* fb     = (const float*)d_in[13];
    const float* beta   = (const float*)d_in[14];
    float* out = (float*)d_out;

    int N = in_sizes[0] / 9;
    int E = in_sizes[1] / 2;
    int G = in_sizes[4];
    int L = in_sizes[9];
    float invN = 1.f / (float)N;

    cudaFuncSetAttribute(k_gemm, cudaFuncAttributeMaxDynamicSharedMemorySize, GEMM_SMEM);

    int agg_grid = (N + 3) / 4;
    int gemm_grid = (N + 127) / 128;
    int prep_grid = (N * 64 + 255) / 256;

    // launch 0..2: prologue (fused)
    k_init<<<L * 128 + 512 + 2048 + 2048, 128>>>(x, aemb, bemb, convw, ei, N, E, L);
    k_scan<<<1, 1024>>>(N, E);
    k_scatter<<<(E + 255) / 256, 256>>>(ei, ea, E);

    // launch 3: k_agg layer 0 (target of ncu capture)
    k_agg<<<agg_grid, 128>>>(ts, 0, N);
    k_gemm<<<gemm_grid, 256, GEMM_SMEM>>>(convb, 0, 0, N);

    for (int l = 1; l < L; l++) {
        k_prep<<<prep_grid, 256>>>(gammas, betas, l - 1, N, invN);
        k_agg<<<agg_grid, 128>>>(ts, l, N);
        k_gemm<<<gemm_grid, 256, GEMM_SMEM>>>(convb, l, 1, N);
    }

    int P = 256;
    int nlen = (N + P - 1) / P;
    k_pool<<<P, 128>>>(batch, gammas, betas, L - 1, N, nlen, invN);
    k_final<<<(G + 3) / 4, 128>>>(fw, fb, beta, rf, out, G);
    k_cleanup<<<512, 256>>>(N, G);
}

// round 6
// speedup vs baseline: 2.2539x; 1.2450x over previous
#include <cuda_runtime.h>
#include <cuda_fp16.h>
#include <cstdint>

#define MAXN 131072
#define MAXE 655360
#define GMAX 1024

// ---------------- static scratch (zero-initialized at module load) ----------------
__device__ float   g_h[(size_t)MAXN * 128];        // residual stream (fp32)
__device__ __half  g_h2[(size_t)MAXN * 128];       // relu(BN(h)) for gather (fp16)
__device__ __half  g_t[(size_t)MAXN * 128];        // GEMM A operand (fp16)
__device__ __half  g_ecomb[512 * 128];             // combined bond-emb table (fp16)
__device__ int2    g_epack[MAXE];                  // {src, combo}, CSR(dst) order
__device__ int     g_rowptr[MAXN + 1];
__device__ int     g_deg[MAXN];                    // zeroed by cleanup
__device__ int     g_incl[MAXN];
__device__ int     g_cursor[MAXN];                 // zeroed by cleanup
__device__ int     g_bsum[256];
__device__ __half  g_Wt[8 * 128 * 128];            // Wt[l][n][k] = W[l][k][n] (fp16)
__device__ float   g_bnsum[8 * 128];               // per-layer stats (cleanup-zeroed)
__device__ float   g_bnsq[8 * 128];
__device__ float   g_acc[(size_t)GMAX * 128];      // pooling accum (cleanup-zeroed)
__device__ int     g_cnt[GMAX];

// ---------------- helpers ----------------
__device__ __forceinline__ uint32_t smem_u32(const void* p) {
    uint32_t a;
    asm("{ .reg .u64 t; cvta.to.shared.u64 t, %1; cvt.u32.u64 %0, t; }" : "=r"(a) : "l"(p));
    return a;
}

#define LDMATRIX_X4(r0, r1, r2, r3, addr) \
    asm volatile("ldmatrix.sync.aligned.m8n8.x4.shared.b16 {%0,%1,%2,%3}, [%4];" \
                 : "=r"(r0), "=r"(r1), "=r"(r2), "=r"(r3) : "r"(addr))

#define MMA_F16(c, a0, a1, a2, a3, b0, b1) \
    asm volatile("mma.sync.aligned.m16n8k16.row.col.f32.f16.f16.f32 " \
                 "{%0,%1,%2,%3}, {%4,%5,%6,%7}, {%8,%9}, {%0,%1,%2,%3};" \
                 : "+f"((c)[0]), "+f"((c)[1]), "+f"((c)[2]), "+f"((c)[3]) \
                 : "r"(a0), "r"(a1), "r"(a2), "r"(a3), "r"(b0), "r"(b1))

#define EX2_F16X2(dst, src) \
    asm("ex2.approx.f16x2 %0, %1;" : "=r"(dst) : "r"(src))

// ---------------- fused init: convW + combined bond table + h0 + degree hist --------
__global__ void __launch_bounds__(128) k_init(const int* __restrict__ x,
                                              const float* __restrict__ aemb,
                                              const float* __restrict__ bemb,
                                              const float* __restrict__ w,
                                              const int* __restrict__ ei,
                                              int N, int E, int L) {
    int b = blockIdx.x;
    int tid = threadIdx.x;
    int gcw = L * 128;
    if (b < gcw) {                       // transpose conv weights -> fp16
        int i = b * 128 + tid;
        int l = i >> 14, r = i & 16383, n = r >> 7, k = r & 127;
        g_Wt[i] = __float2half(w[(l << 14) + (k << 7) + n]);
        return;
    }
    b -= gcw;
    if (b < 512) {                       // combined bond-embedding table
        int a0 = b & 7, a1 = (b >> 3) & 7, a2 = (b >> 6) & 7;
        float s = __ldg(bemb + (0 * 8 + a0) * 128 + tid)
                + __ldg(bemb + (1 * 8 + a1) * 128 + tid)
                + __ldg(bemb + (2 * 8 + a2) * 128 + tid);
        g_ecomb[b * 128 + tid] = __float2half(s);
        return;
    }
    b -= 512;
    if (b < 2048) {                      // atom encoder -> h (fp32) and h2 (fp16)
        for (int n = b; n < N; n += 2048) {
            float s = 0.f;
#pragma unroll
            for (int f = 0; f < 9; f++) {
                int xi = __ldg(x + n * 9 + f);
                s += __ldg(aemb + ((size_t)f * 64 + xi) * 128 + tid);
            }
            g_h[(size_t)n * 128 + tid] = s;
            g_h2[(size_t)n * 128 + tid] = __float2half(s);
        }
        return;
    }
    b -= 2048;
    for (int e = b * 128 + tid; e < E; e += 2048 * 128)
        atomicAdd(g_deg + __ldg(ei + E + e), 1);
}

// ---------------- 3-kernel parallel exclusive scan ----------------
__global__ void k_scan1(int N) {
    __shared__ int sm[1024];
    int i = blockIdx.x * 1024 + threadIdx.x;
    int v = (i < N) ? g_deg[i] : 0;
    sm[threadIdx.x] = v;
    __syncthreads();
    for (int off = 1; off < 1024; off <<= 1) {
        int t = (threadIdx.x >= off) ? sm[threadIdx.x - off] : 0;
        __syncthreads();
        if (threadIdx.x >= off) sm[threadIdx.x] += t;
        __syncthreads();
    }
    if (i < N) g_incl[i] = sm[threadIdx.x];
    if (threadIdx.x == 1023) g_bsum[blockIdx.x] = sm[1023];
}

__global__ void k_scan2(int nb) {
    __shared__ int sm[256];
    int t = threadIdx.x;
    int v = (t < nb) ? g_bsum[t] : 0;
    sm[t] = v;
    __syncthreads();
    for (int off = 1; off < 256; off <<= 1) {
        int u = (t >= off) ? sm[t - off] : 0;
        __syncthreads();
        if (t >= off) sm[t] += u;
        __syncthreads();
    }
    if (t < nb) g_bsum[t] = sm[t] - v;  // exclusive block offsets
}

__global__ void k_scan3(int N, int E) {
    int i = blockIdx.x * 1024 + threadIdx.x;
    if (i < N) g_rowptr[i] = g_incl[i] - g_deg[i] + g_bsum[blockIdx.x];
    if (i == 0) g_rowptr[N] = E;
}

// ---------------- scatter edges into CSR order (packed src+attr) ----------------
__global__ void k_scatter(const int* __restrict__ ei, const int* __restrict__ ea, int E) {
    int e = blockIdx.x * blockDim.x + threadIdx.x;
    if (e >= E) return;
    int d = __ldg(ei + E + e);
    int pos = g_rowptr[d] + atomicAdd(g_cursor + d, 1);
    int a0 = __ldg(ea + e * 3 + 0), a1 = __ldg(ea + e * 3 + 1), a2 = __ldg(ea + e * 3 + 2);
    g_epack[pos] = make_int2(__ldg(ei + e), a0 + a1 * 8 + a2 * 64);
}

// ---------------- softmax aggregation (warp/node, packed f16x2, f16x2 exp) -------
__device__ __forceinline__ void aggproc(uint2 su, uint2 eu, uint32_t tt2u,
                                        float& s0, float& s1, float& s2, float& s3,
                                        float& w0, float& w1, float& w2, float& w3) {
    __half2 h01 = *reinterpret_cast<__half2*>(&su.x);
    __half2 h23 = *reinterpret_cast<__half2*>(&su.y);
    __half2 e01 = *reinterpret_cast<__half2*>(&eu.x);
    __half2 e23 = *reinterpret_cast<__half2*>(&eu.y);
    __half2 z = __half2half2(__ushort_as_half(0));
    __half2 q01 = __hmax2(__hadd2(h01, e01), z);     // relu(h+e), f16x2
    __half2 q23 = __hmax2(__hadd2(h23, e23), z);
    __half2 tt2 = *reinterpret_cast<__half2*>(&tt2u);
    __half2 qt01 = __hmul2(q01, tt2);                // q * t*log2(e)
    __half2 qt23 = __hmul2(q23, tt2);
    uint32_t x01u, x23u;
    EX2_F16X2(x01u, *reinterpret_cast<uint32_t*>(&qt01));
    EX2_F16X2(x23u, *reinterpret_cast<uint32_t*>(&qt23));
    float2 xf01 = __half22float2(*reinterpret_cast<__half2*>(&x01u));
    float2 xf23 = __half22float2(*reinterpret_cast<__half2*>(&x23u));
    float2 qf01 = __half22float2(q01);
    float2 qf23 = __half22float2(q23);
    s0 += xf01.x; s1 += xf01.y; s2 += xf23.x; s3 += xf23.y;
    w0 = fmaf(xf01.x, qf01.x, w0);
    w1 = fmaf(xf01.y, qf01.y, w1);
    w2 = fmaf(xf23.x, qf23.x, w2);
    w3 = fmaf(xf23.y, qf23.y, w3);
}

__global__ void __launch_bounds__(128) k_agg(const float* __restrict__ ts, int l, int N) {
    int gw = (blockIdx.x << 2) + (threadIdx.x >> 5);
    if (gw >= N) return;
    int lane = threadIdx.x & 31;
    int c0 = lane << 2;
    float ttf = __ldg(ts + l) * 1.44269504088896f;   // t * log2(e)
    __half2 tt2h = __float2half2_rn(ttf);
    uint32_t tt2u = *reinterpret_cast<uint32_t*>(&tt2h);

    uint2 hu = *(const uint2*)(g_h2 + (size_t)gw * 128 + c0);
    float2 hi01 = __half22float2(*reinterpret_cast<__half2*>(&hu.x));
    float2 hi23 = __half22float2(*reinterpret_cast<__half2*>(&hu.y));

    int p0 = __ldg(g_rowptr + gw), p1 = __ldg(g_rowptr + gw + 1);
    float s0 = 0.f, s1 = 0.f, s2 = 0.f, s3 = 0.f;
    float w0 = 0.f, w1 = 0.f, w2 = 0.f, w3 = 0.f;

    int p = p0;
    for (; p + 2 <= p1; p += 2) {
        int2 eA = __ldg(g_epack + p);
        int2 eB = __ldg(g_epack + p + 1);
        uint2 suA = *(const uint2*)(g_h2 + (size_t)eA.x * 128 + c0);
        uint2 euA = *(const uint2*)(g_ecomb + (size_t)eA.y * 128 + c0);
        uint2 suB = *(const uint2*)(g_h2 + (size_t)eB.x * 128 + c0);
        uint2 euB = *(const uint2*)(g_ecomb + (size_t)eB.y * 128 + c0);
        aggproc(suA, euA, tt2u, s0, s1, s2, s3, w0, w1, w2, w3);
        aggproc(suB, euB, tt2u, s0, s1, s2, s3, w0, w1, w2, w3);
    }
    if (p < p1) {
        int2 eA = __ldg(g_epack + p);
        uint2 su = *(const uint2*)(g_h2 + (size_t)eA.x * 128 + c0);
        uint2 eu = *(const uint2*)(g_ecomb + (size_t)eA.y * 128 + c0);
        aggproc(su, eu, tt2u, s0, s1, s2, s3, w0, w1, w2, w3);
    }

    float o0 = hi01.x + w0 / (s0 + 1e-16f);
    float o1 = hi01.y + w1 / (s1 + 1e-16f);
    float o2 = hi23.x + w2 / (s2 + 1e-16f);
    float o3 = hi23.y + w3 / (s3 + 1e-16f);

    __half2 t01 = __floats2half2_rn(o0, o1);
    __half2 t23 = __floats2half2_rn(o2, o3);
    uint2 st;
    st.x = *reinterpret_cast<uint32_t*>(&t01);
    st.y = *reinterpret_cast<uint32_t*>(&t23);
    *(uint2*)(g_t + (size_t)gw * 128 + c0) = st;
}

// ---------------- mma.sync GEMM + fused BN stats ----------------
#define GEMM_SMEM (2 * 128 * 272 + 1024)

__global__ void __launch_bounds__(256) k_gemm(const float* __restrict__ conv_b,
                                              int l, int add_res, int N) {
    extern __shared__ char smem[];
    char* sA = smem;
    char* sB = smem + 128 * 272;
    float* sbn = (float*)(smem + 2 * 128 * 272);   // [256]: sums | sumsq
    int tid = threadIdx.x;
    int node0 = blockIdx.x * 128;

    if (tid < 256) sbn[tid] = 0.f;

    const uint4* asrc = (const uint4*)(g_t + (size_t)node0 * 128);
    const uint4* bsrc = (const uint4*)(g_Wt + (size_t)l * 16384);
#pragma unroll
    for (int i = tid; i < 2048; i += 256) {
        int row = i >> 4, cq = i & 15;
        *(uint4*)(sA + row * 272 + cq * 16) = asrc[i];
        *(uint4*)(sB + row * 272 + cq * 16) = bsrc[i];
    }
    __syncthreads();

    int wid = tid >> 5, lane = tid & 31;
    int wm = wid >> 1, wn = wid & 1;           // 4 x 2 warp grid
    uint32_t sab = smem_u32(sA), sbb = smem_u32(sB);

    float acc[2][8][4];
#pragma unroll
    for (int mt = 0; mt < 2; mt++)
#pragma unroll
        for (int nt = 0; nt < 8; nt++)
#pragma unroll
            for (int q = 0; q < 4; q++) acc[mt][nt][q] = 0.f;

    int lrow = lane & 15, lhalf = (lane >> 4) << 3;

#pragma unroll
    for (int ks = 0; ks < 8; ks++) {
        int k0 = ks * 16;
        uint32_t a[2][4];
#pragma unroll
        for (int mt = 0; mt < 2; mt++) {
            int r = wm * 32 + mt * 16 + lrow;
            uint32_t addr = sab + r * 272 + (k0 + lhalf) * 2;
            LDMATRIX_X4(a[mt][0], a[mt][1], a[mt][2], a[mt][3], addr);
        }
        uint32_t bq[4][4];
#pragma unroll
        for (int nq = 0; nq < 4; nq++) {
            int nr = wn * 64 + nq * 16 + lrow;
            uint32_t addr = sbb + nr * 272 + (k0 + lhalf) * 2;
            LDMATRIX_X4(bq[nq][0], bq[nq][1], bq[nq][2], bq[nq][3], addr);
        }
#pragma unroll
        for (int mt = 0; mt < 2; mt++)
#pragma unroll
            for (int nq = 0; nq < 4; nq++) {
                MMA_F16(acc[mt][nq * 2 + 0], a[mt][0], a[mt][1], a[mt][2], a[mt][3],
                        bq[nq][0], bq[nq][2]);
                MMA_F16(acc[mt][nq * 2 + 1], a[mt][0], a[mt][1], a[mt][2], a[mt][3],
                        bq[nq][1], bq[nq][3]);
            }
    }

    // epilogue: bias (+residual) -> h, accumulate BN stats
    int qrow = lane >> 2, qcol = (lane & 3) * 2;
    float colS[16], colQ[16];
#pragma unroll
    for (int i = 0; i < 16; i++) { colS[i] = 0.f; colQ[i] = 0.f; }

#pragma unroll
    for (int mt = 0; mt < 2; mt++) {
#pragma unroll
        for (int nt = 0; nt < 8; nt++) {
            int col = wn * 64 + nt * 8 + qcol;
            float2 bv = *(const float2*)(conv_b + l * 128 + col);
            int row0 = node0 + wm * 32 + mt * 16 + qrow;
#pragma unroll
            for (int hh = 0; hh < 2; hh++) {
                int row = row0 + hh * 8;
                if (row < N) {
                    float* dst = g_h + (size_t)row * 128 + col;
                    float vx = acc[mt][nt][hh * 2 + 0] + bv.x;
                    float vy = acc[mt][nt][hh * 2 + 1] + bv.y;
                    if (add_res) {
                        float2 r = *(const float2*)dst;
                        vx += r.x; vy += r.y;
                    }
                    float2 o; o.x = vx; o.y = vy;
                    *(float2*)dst = o;
                    colS[nt * 2 + 0] += vx;
                    colQ[nt * 2 + 0] = fmaf(vx, vx, colQ[nt * 2 + 0]);
                    colS[nt * 2 + 1] += vy;
                    colQ[nt * 2 + 1] = fmaf(vy, vy, colQ[nt * 2 + 1]);
                }
            }
        }
    }

#pragma unroll
    for (int i = 0; i < 16; i++) {
        float vs = colS[i], vq = colQ[i];
        vs += __shfl_xor_sync(0xFFFFFFFFu, vs, 4);
        vs += __shfl_xor_sync(0xFFFFFFFFu, vs, 8);
        vs += __shfl_xor_sync(0xFFFFFFFFu, vs, 16);
        vq += __shfl_xor_sync(0xFFFFFFFFu, vq, 4);
        vq += __shfl_xor_sync(0xFFFFFFFFu, vq, 8);
        vq += __shfl_xor_sync(0xFFFFFFFFu, vq, 16);
        if (lane < 4) {
            int col = wn * 64 + (i >> 1) * 8 + lane * 2 + (i & 1);
            atomicAdd(sbn + col, vs);
            atomicAdd(sbn + 128 + col, vq);
        }
    }
    __syncthreads();
    if (tid < 128) {
        atomicAdd(g_bnsum + l * 128 + tid, sbn[tid]);
        atomicAdd(g_bnsq + l * 128 + tid, sbn[128 + tid]);
    }
}

// ---------------- h2 = fp16(relu(BN(h))) using stats slot l ----------------
__global__ void k_prep(const float* __restrict__ gammas, const float* __restrict__ betas,
                       int l, int N, float invN) {
    int idx = blockIdx.x * blockDim.x + threadIdx.x;   // N*64 channel pairs
    if (idx >= N * 64) return;
    int row = idx >> 6, cp = (idx & 63) << 1;
    float2 sm = *(const float2*)(g_bnsum + l * 128 + cp);
    float2 sq = *(const float2*)(g_bnsq + l * 128 + cp);
    float2 ga = *(const float2*)(gammas + l * 128 + cp);
    float2 be = *(const float2*)(betas + l * 128 + cp);
    float mu0 = sm.x * invN, mu1 = sm.y * invN;
    float va0 = sq.x * invN - mu0 * mu0, va1 = sq.y * invN - mu1 * mu1;
    float sc0 = rsqrtf(va0 + 1e-5f) * ga.x, sc1 = rsqrtf(va1 + 1e-5f) * ga.y;
    float sh0 = be.x - mu0 * sc0, sh1 = be.y - mu1 * sc1;
    float2 v = *(const float2*)(g_h + (size_t)row * 128 + cp);
    v.x = fmaxf(fmaf(v.x, sc0, sh0), 0.f);
    v.y = fmaxf(fmaf(v.y, sc1, sh1), 0.f);
    *(__half2*)(g_h2 + (size_t)row * 128 + cp) = __floats2half2_rn(v.x, v.y);
}

// ---------------- pooling (final BN inline) + head ----------------
__global__ void k_pool(const int* __restrict__ batch, const float* __restrict__ gammas,
                       const float* __restrict__ betas, int l, int N, int nlen, float invN) {
    int c = threadIdx.x;
    int n0 = blockIdx.x * nlen, n1 = min(N, n0 + nlen);
    if (n0 >= n1) return;
    float sm = g_bnsum[l * 128 + c], sq = g_bnsq[l * 128 + c];
    float mu = sm * invN;
    float var = sq * invN - mu * mu;
    float sc = rsqrtf(var + 1e-5f) * __ldg(gammas + l * 128 + c);
    float sh = __ldg(betas + l * 128 + c) - mu * sc;
    int cur = __ldg(batch + n0);
    float acc = 0.f;
    int cnt = 0;
    for (int n = n0; n < n1; n++) {
        int gg = __ldg(batch + n);
        if (gg != cur) {
            atomicAdd(g_acc + (size_t)cur * 128 + c, acc);
            if (c == 0) atomicAdd(g_cnt + cur, cnt);
            acc = 0.f; cnt = 0; cur = gg;
        }
        float v = fmaxf(fmaf(g_h[(size_t)n * 128 + c], sc, sh), 0.f);
        acc += v;
        cnt++;
    }
    atomicAdd(g_acc + (size_t)cur * 128 + c, acc);
    if (c == 0) atomicAdd(g_cnt + cur, cnt);
}

__global__ void k_final(const float* __restrict__ fw, const float* __restrict__ fb,
                        const float* __restrict__ beta, const float* __restrict__ rf,
                        float* __restrict__ out, int G) {
    int wid = threadIdx.x >> 5, lane = threadIdx.x & 31;
    int g = blockIdx.x * 4 + wid;
    if (g >= G) return;
    float4 a = ((const float4*)(g_acc + (size_t)g * 128))[lane];
    float4 w = ((const float4*)fw)[lane];
    float dot = a.x * w.x + a.y * w.y + a.z * w.z + a.w * w.w;
#pragma unroll
    for (int o = 16; o > 0; o >>= 1) dot += __shfl_down_sync(0xFFFFFFFFu, dot, o);
    if (lane == 0) {
        float cntf = fmaxf((float)g_cnt[g], 1.f);
        float pred = dot / cntf + fb[0];
        float sg = 1.f / (1.f + __expf(-pred));
        float b = beta[0];
        out[g] = (1.f - b) * sg + b * rf[g];
    }
}

// ---------------- restore zeroed state for next (graph-replayed) call --------------
__global__ void k_cleanup(int N, int G) {
    int i = blockIdx.x * blockDim.x + threadIdx.x;
    int stride = gridDim.x * blockDim.x;
    for (int j = i; j < N; j += stride) { g_deg[j] = 0; g_cursor[j] = 0; }
    for (int j = i; j < G * 128; j += stride) g_acc[j] = 0.f;
    for (int j = i; j < G; j += stride) g_cnt[j] = 0;
    for (int j = i; j < 1024; j += stride) { g_bnsum[j] = 0.f; g_bnsq[j] = 0.f; }
}

// ---------------- launch ----------------
extern "C" void kernel_launch(void* const* d_in, const int* in_sizes, int n_in,
                              void* d_out, int out_size) {
    const int*   x      = (const int*)d_in[0];
    const int*   ei     = (const int*)d_in[1];
    const int*   ea     = (const int*)d_in[2];
    const int*   batch  = (const int*)d_in[3];
    const float* rf     = (const float*)d_in[4];
    const float* aemb   = (const float*)d_in[5];
    const float* bemb   = (const float*)d_in[6];
    const float* convw  = (const float*)d_in[7];
    const float* convb  = (const float*)d_in[8];
    const float* ts     = (const float*)d_in[9];
    const float* gammas = (const float*)d_in[10];
    const float* betas  = (const float*)d_in[11];
    const float* fw     = (const float*)d_in[12];
    const float* fb     = (const float*)d_in[13];
    const float* beta   = (const float*)d_in[14];
    float* out = (float*)d_out;

    int N = in_sizes[0] / 9;
    int E = in_sizes[1] / 2;
    int G = in_sizes[4];
    int L = in_sizes[9];
    float invN = 1.f / (float)N;

    cudaFuncSetAttribute(k_gemm, cudaFuncAttributeMaxDynamicSharedMemorySize, GEMM_SMEM);

    int agg_grid = (N + 3) / 4;
    int gemm_grid = (N + 127) / 128;
    int prep_grid = (N * 64 + 255) / 256;
    int nb = (N + 1023) / 1024;

    k_init<<<L * 128 + 512 + 2048 + 2048, 128>>>(x, aemb, bemb, convw, ei, N, E, L);
    k_scan1<<<nb, 1024>>>(N);
    k_scan2<<<1, 256>>>(nb);
    k_scan3<<<nb, 1024>>>(N, E);
    k_scatter<<<(E + 255) / 256, 256>>>(ei, ea, E);

    k_agg<<<agg_grid, 128>>>(ts, 0, N);
    k_gemm<<<gemm_grid, 256, GEMM_SMEM>>>(convb, 0, 0, N);

    for (int l = 1; l < L; l++) {
        k_prep<<<prep_grid, 256>>>(gammas, betas, l - 1, N, invN);
        k_agg<<<agg_grid, 128>>>(ts, l, N);
        k_gemm<<<gemm_grid, 256, GEMM_SMEM>>>(convb, l, 1, N);
    }

    int P = 512;
    int nlen = (N + P - 1) / P;
    k_pool<<<P, 128>>>(batch, gammas, betas, L - 1, N, nlen, invN);
    k_final<<<(G + 3) / 4, 128>>>(fw, fb, beta, rf, out, G);
    k_cleanup<<<512, 256>>>(N, G);
}

// round 8
// speedup vs baseline: 2.7297x; 1.2111x over previous
#include <cuda_runtime.h>
#include <cuda_fp16.h>
#include <cstdint>

#define MAXN 131072
#define MAXE 655360
#define GMAX 1024

// ---------------- static scratch (zero-initialized at module load) ----------------
__device__ __half  g_h[(size_t)MAXN * 128];        // residual stream (fp16)
__device__ __half  g_h2[(size_t)MAXN * 128];       // relu(BN(h)) for gather (fp16)
__device__ __half  g_t[(size_t)MAXN * 128];        // GEMM A operand (fp16)
__device__ __half  g_ecomb[512 * 128];             // combined bond-emb table (fp16)
__device__ int2    g_epack[MAXE];                  // {src, combo}, CSR(dst) order
__device__ int     g_rowptr[MAXN + 1];
__device__ int     g_deg[MAXN];                    // zeroed by cleanup
__device__ int     g_cursor[MAXN];                 // zeroed by cleanup
__device__ int     g_scanagg[128];
__device__ int     g_scanpre[128];
__device__ volatile int g_scanflag[128];           // zeroed by cleanup
__device__ __half  g_Wt[8 * 128 * 128];            // Wt[l][n][k] = W[l][k][n] (fp16)
__device__ float   g_bnsum[8 * 128];               // per-layer stats (cleanup-zeroed)
__device__ float   g_bnsq[8 * 128];
__device__ float   g_acc[(size_t)GMAX * 128];      // pooling accum (cleanup-zeroed)
__device__ int     g_cnt[GMAX];

// ---------------- helpers ----------------
__device__ __forceinline__ uint32_t smem_u32(const void* p) {
    uint32_t a;
    asm("{ .reg .u64 t; cvta.to.shared.u64 t, %1; cvt.u32.u64 %0, t; }" : "=r"(a) : "l"(p));
    return a;
}

#define LDMATRIX_X4(r0, r1, r2, r3, addr) \
    asm volatile("ldmatrix.sync.aligned.m8n8.x4.shared.b16 {%0,%1,%2,%3}, [%4];" \
                 : "=r"(r0), "=r"(r1), "=r"(r2), "=r"(r3) : "r"(addr))

#define MMA_F16(c, a0, a1, a2, a3, b0, b1) \
    asm volatile("mma.sync.aligned.m16n8k16.row.col.f32.f16.f16.f32 " \
                 "{%0,%1,%2,%3}, {%4,%5,%6,%7}, {%8,%9}, {%0,%1,%2,%3};" \
                 : "+f"((c)[0]), "+f"((c)[1]), "+f"((c)[2]), "+f"((c)[3]) \
                 : "r"(a0), "r"(a1), "r"(a2), "r"(a3), "r"(b0), "r"(b1))

#define EX2_F16X2(dst, src) \
    asm("ex2.approx.f16x2 %0, %1;" : "=r"(dst) : "r"(src))

// ---------------- fused init: convW + combined bond table + h0 + degree hist --------
__global__ void __launch_bounds__(128) k_init(const int* __restrict__ x,
                                              const float* __restrict__ aemb,
                                              const float* __restrict__ bemb,
                                              const float* __restrict__ w,
                                              const int* __restrict__ ei,
                                              int N, int E, int L) {
    int b = blockIdx.x;
    int tid = threadIdx.x;
    int gcw = L * 128;
    if (b < gcw) {                       // transpose conv weights -> fp16
        int i = b * 128 + tid;
        int l = i >> 14, r = i & 16383, n = r >> 7, k = r & 127;
        g_Wt[i] = __float2half(w[(l << 14) + (k << 7) + n]);
        return;
    }
    b -= gcw;
    if (b < 512) {                       // combined bond-embedding table
        int a0 = b & 7, a1 = (b >> 3) & 7, a2 = (b >> 6) & 7;
        float s = __ldg(bemb + (0 * 8 + a0) * 128 + tid)
                + __ldg(bemb + (1 * 8 + a1) * 128 + tid)
                + __ldg(bemb + (2 * 8 + a2) * 128 + tid);
        g_ecomb[b * 128 + tid] = __float2half(s);
        return;
    }
    b -= 512;
    if (b < 2048) {                      // atom encoder -> h and h2 (fp16)
        for (int n = b; n < N; n += 2048) {
            float s = 0.f;
#pragma unroll
            for (int f = 0; f < 9; f++) {
                int xi = __ldg(x + n * 9 + f);
                s += __ldg(aemb + ((size_t)f * 64 + xi) * 128 + tid);
            }
            __half hs = __float2half(s);
            g_h[(size_t)n * 128 + tid] = hs;
            g_h2[(size_t)n * 128 + tid] = hs;
        }
        return;
    }
    b -= 2048;
    for (int e = b * 128 + tid; e < E; e += 2048 * 128)
        atomicAdd(g_deg + __ldg(ei + E + e), 1);
}

// ---------------- single-kernel decoupled-lookback exclusive scan ----------------
// grid must be <= SM count so all blocks are resident (98 blocks for N=100k)
__global__ void __launch_bounds__(1024) k_scan(int N, int E) {
    __shared__ int warp_tot[32];
    __shared__ int s_prefix;
    int b = blockIdx.x, tid = threadIdx.x, lane = tid & 31, wid = tid >> 5;
    int i = b * 1024 + tid;
    int v = (i < N) ? g_deg[i] : 0;
    int xv = v;
#pragma unroll
    for (int o = 1; o < 32; o <<= 1) {
        int y = __shfl_up_sync(0xFFFFFFFFu, xv, o);
        if (lane >= o) xv += y;
    }
    if (lane == 31) warp_tot[wid] = xv;
    __syncthreads();
    if (wid == 0) {
        int wv = warp_tot[lane];
#pragma unroll
        for (int o = 1; o < 32; o <<= 1) {
            int y = __shfl_up_sync(0xFFFFFFFFu, wv, o);
            if (lane >= o) wv += y;
        }
        warp_tot[lane] = wv;
    }
    __syncthreads();
    int woff = wid ? warp_tot[wid - 1] : 0;
    int incl = woff + xv;               // inclusive within block
    int total = warp_tot[31];
    if (tid == 0) {
        g_scanagg[b] = total;
        __threadfence();
        g_scanflag[b] = 1;
        int sum = 0;
        for (int j = b - 1; j >= 0; j--) {
            int f;
            while ((f = g_scanflag[j]) == 0) {}
            if (f == 2) { sum += ((volatile int*)g_scanpre)[j]; break; }
            sum += ((volatile int*)g_scanagg)[j];
        }
        g_scanpre[b] = sum + total;
        __threadfence();
        g_scanflag[b] = 2;
        s_prefix = sum;
    }
    __syncthreads();
    int excl = s_prefix + incl - v;
    if (i < N) g_rowptr[i] = excl;
    if (i == N - 1) g_rowptr[N] = E;
}

// ---------------- scatter edges into CSR order (packed src+attr) ----------------
__global__ void k_scatter(const int* __restrict__ ei, const int* __restrict__ ea, int E) {
    int e = blockIdx.x * blockDim.x + threadIdx.x;
    if (e >= E) return;
    int d = __ldg(ei + E + e);
    int pos = g_rowptr[d] + atomicAdd(g_cursor + d, 1);
    int a0 = __ldg(ea + e * 3 + 0), a1 = __ldg(ea + e * 3 + 1), a2 = __ldg(ea + e * 3 + 2);
    g_epack[pos] = make_int2(__ldg(ei + e), a0 + a1 * 8 + a2 * 64);
}

// ---------------- softmax aggregation (warp/node, all-f16x2, scaled exp) -------
__global__ void __launch_bounds__(128) k_agg(const float* __restrict__ ts, int l, int N) {
    int gw = (blockIdx.x << 2) + (threadIdx.x >> 5);
    if (gw >= N) return;
    int lane = threadIdx.x & 31;
    int c0 = lane << 2;
    float ttf = __ldg(ts + l) * 1.44269504088896f;   // t * log2(e)
    __half2 tt2 = __float2half2_rn(ttf);
    __half2 nb6 = __float2half2_rn(-6.0f);           // 2^-6 pre-scale (cancels in w/s)
    __half2 z = __float2half2_rn(0.f);

    uint2 hu = *(const uint2*)(g_h2 + (size_t)gw * 128 + c0);
    float2 hi01 = __half22float2(*reinterpret_cast<__half2*>(&hu.x));
    float2 hi23 = __half22float2(*reinterpret_cast<__half2*>(&hu.y));

    int p0 = __ldg(g_rowptr + gw), p1 = __ldg(g_rowptr + gw + 1);
    __half2 s01 = z, s23 = z, w01 = z, w23 = z;

#pragma unroll 2
    for (int p = p0; p < p1; p++) {
        int2 ep = __ldg(g_epack + p);
        uint2 su = *(const uint2*)(g_h2 + (size_t)ep.x * 128 + c0);
        uint2 eu = *(const uint2*)(g_ecomb + (size_t)ep.y * 128 + c0);
        __half2 q01 = __hmax2(__hadd2(*reinterpret_cast<__half2*>(&su.x),
                                      *reinterpret_cast<__half2*>(&eu.x)), z);
        __half2 q23 = __hmax2(__hadd2(*reinterpret_cast<__half2*>(&su.y),
                                      *reinterpret_cast<__half2*>(&eu.y)), z);
        __half2 qt01 = __hfma2(q01, tt2, nb6);
        __half2 qt23 = __hfma2(q23, tt2, nb6);
        uint32_t x01u, x23u;
        EX2_F16X2(x01u, *reinterpret_cast<uint32_t*>(&qt01));
        EX2_F16X2(x23u, *reinterpret_cast<uint32_t*>(&qt23));
        __half2 x01 = *reinterpret_cast<__half2*>(&x01u);
        __half2 x23 = *reinterpret_cast<__half2*>(&x23u);
        s01 = __hadd2(s01, x01);
        s23 = __hadd2(s23, x23);
        w01 = __hfma2(x01, q01, w01);
        w23 = __hfma2(x23, q23, w23);
    }

    float2 sf01 = __half22float2(s01), sf23 = __half22float2(s23);
    float2 wf01 = __half22float2(w01), wf23 = __half22float2(w23);
    float o0 = hi01.x + wf01.x / (sf01.x + 1e-16f);
    float o1 = hi01.y + wf01.y / (sf01.y + 1e-16f);
    float o2 = hi23.x + wf23.x / (sf23.x + 1e-16f);
    float o3 = hi23.y + wf23.y / (sf23.y + 1e-16f);

    __half2 t01 = __floats2half2_rn(o0, o1);
    __half2 t23 = __floats2half2_rn(o2, o3);
    uint2 st;
    st.x = *reinterpret_cast<uint32_t*>(&t01);
    st.y = *reinterpret_cast<uint32_t*>(&t23);
    *(uint2*)(g_t + (size_t)gw * 128 + c0) = st;
}

// ---------------- mma.sync GEMM + fused BN stats (h fp16) ----------------
#define GEMM_SMEM (2 * 128 * 272 + 1024)

__global__ void __launch_bounds__(256) k_gemm(const float* __restrict__ conv_b,
                                              int l, int add_res, int N) {
    extern __shared__ char smem[];
    char* sA = smem;
    char* sB = smem + 128 * 272;
    float* sbn = (float*)(smem + 2 * 128 * 272);   // [256]: sums | sumsq
    int tid = threadIdx.x;
    int node0 = blockIdx.x * 128;

    if (tid < 256) sbn[tid] = 0.f;

    const uint4* asrc = (const uint4*)(g_t + (size_t)node0 * 128);
    const uint4* bsrc = (const uint4*)(g_Wt + (size_t)l * 16384);
#pragma unroll
    for (int i = tid; i < 2048; i += 256) {
        int row = i >> 4, cq = i & 15;
        *(uint4*)(sA + row * 272 + cq * 16) = asrc[i];
        *(uint4*)(sB + row * 272 + cq * 16) = bsrc[i];
    }
    __syncthreads();

    int wid = tid >> 5, lane = tid & 31;
    int wm = wid >> 1, wn = wid & 1;           // 4 x 2 warp grid
    uint32_t sab = smem_u32(sA), sbb = smem_u32(sB);

    float acc[2][8][4];
#pragma unroll
    for (int mt = 0; mt < 2; mt++)
#pragma unroll
        for (int nt = 0; nt < 8; nt++)
#pragma unroll
            for (int q = 0; q < 4; q++) acc[mt][nt][q] = 0.f;

    int lrow = lane & 15, lhalf = (lane >> 4) << 3;

#pragma unroll
    for (int ks = 0; ks < 8; ks++) {
        int k0 = ks * 16;
        uint32_t a[2][4];
#pragma unroll
        for (int mt = 0; mt < 2; mt++) {
            int r = wm * 32 + mt * 16 + lrow;
            uint32_t addr = sab + r * 272 + (k0 + lhalf) * 2;
            LDMATRIX_X4(a[mt][0], a[mt][1], a[mt][2], a[mt][3], addr);
        }
        uint32_t bq[4][4];
#pragma unroll
        for (int nq = 0; nq < 4; nq++) {
            int nr = wn * 64 + nq * 16 + lrow;
            uint32_t addr = sbb + nr * 272 + (k0 + lhalf) * 2;
            LDMATRIX_X4(bq[nq][0], bq[nq][1], bq[nq][2], bq[nq][3], addr);
        }
#pragma unroll
        for (int mt = 0; mt < 2; mt++)
#pragma unroll
            for (int nq = 0; nq < 4; nq++) {
                MMA_F16(acc[mt][nq * 2 + 0], a[mt][0], a[mt][1], a[mt][2], a[mt][3],
                        bq[nq][0], bq[nq][2]);
                MMA_F16(acc[mt][nq * 2 + 1], a[mt][0], a[mt][1], a[mt][2], a[mt][3],
                        bq[nq][1], bq[nq][3]);
            }
    }

    // epilogue: bias (+residual) -> h (fp16), accumulate BN stats (fp32)
    int qrow = lane >> 2, qcol = (lane & 3) * 2;
    float colS[16], colQ[16];
#pragma unroll
    for (int i = 0; i < 16; i++) { colS[i] = 0.f; colQ[i] = 0.f; }

#pragma unroll
    for (int mt = 0; mt < 2; mt++) {
#pragma unroll
        for (int nt = 0; nt < 8; nt++) {
            int col = wn * 64 + nt * 8 + qcol;
            float2 bv = *(const float2*)(conv_b + l * 128 + col);
            int row0 = node0 + wm * 32 + mt * 16 + qrow;
#pragma unroll
            for (int hh = 0; hh < 2; hh++) {
                int row = row0 + hh * 8;
                if (row < N) {
                    __half* dst = g_h + (size_t)row * 128 + col;
                    float vx = acc[mt][nt][hh * 2 + 0] + bv.x;
                    float vy = acc[mt][nt][hh * 2 + 1] + bv.y;
                    if (add_res) {
                        float2 r = __half22float2(*(const __half2*)dst);
                        vx += r.x; vy += r.y;
                    }
                    *(__half2*)dst = __floats2half2_rn(vx, vy);
                    colS[nt * 2 + 0] += vx;
                    colQ[nt * 2 + 0] = fmaf(vx, vx, colQ[nt * 2 + 0]);
                    colS[nt * 2 + 1] += vy;
                    colQ[nt * 2 + 1] = fmaf(vy, vy, colQ[nt * 2 + 1]);
                }
            }
        }
    }

#pragma unroll
    for (int i = 0; i < 16; i++) {
        float vs = colS[i], vq = colQ[i];
        vs += __shfl_xor_sync(0xFFFFFFFFu, vs, 4);
        vs += __shfl_xor_sync(0xFFFFFFFFu, vs, 8);
        vs += __shfl_xor_sync(0xFFFFFFFFu, vs, 16);
        vq += __shfl_xor_sync(0xFFFFFFFFu, vq, 4);
        vq += __shfl_xor_sync(0xFFFFFFFFu, vq, 8);
        vq += __shfl_xor_sync(0xFFFFFFFFu, vq, 16);
        if (lane < 4) {
            int col = wn * 64 + (i >> 1) * 8 + lane * 2 + (i & 1);
            atomicAdd(sbn + col, vs);
            atomicAdd(sbn + 128 + col, vq);
        }
    }
    __syncthreads();
    if (tid < 128) {
        atomicAdd(g_bnsum + l * 128 + tid, sbn[tid]);
        atomicAdd(g_bnsq + l * 128 + tid, sbn[128 + tid]);
    }
}

// ---------------- h2 = relu(BN(h)), pure f16x2 with smem scale table ----------------
__global__ void __launch_bounds__(256) k_prep(const float* __restrict__ gammas,
                                              const float* __restrict__ betas,
                                              int l, int N, float invN) {
    __shared__ __half2 ssc[64], ssh[64];
    int tid = threadIdx.x;
    if (tid < 64) {
        int cp = tid * 2;
        float2 sm = *(const float2*)(g_bnsum + l * 128 + cp);
        float2 sq = *(const float2*)(g_bnsq + l * 128 + cp);
        float2 ga = *(const float2*)(gammas + l * 128 + cp);
        float2 be = *(const float2*)(betas + l * 128 + cp);
        float mu0 = sm.x * invN, mu1 = sm.y * invN;
        float va0 = sq.x * invN - mu0 * mu0, va1 = sq.y * invN - mu1 * mu1;
        float sc0 = rsqrtf(va0 + 1e-5f) * ga.x, sc1 = rsqrtf(va1 + 1e-5f) * ga.y;
        float sh0 = be.x - mu0 * sc0, sh1 = be.y - mu1 * sc1;
        ssc[tid] = __floats2half2_rn(sc0, sc1);
        ssh[tid] = __floats2half2_rn(sh0, sh1);
    }
    __syncthreads();
    int idx = blockIdx.x * 256 + tid;        // N*16 units of 8 channels
    if (idx >= N * 16) return;
    int row = idx >> 4, c8 = (idx & 15) << 3;
    uint4 hv = *(const uint4*)(g_h + (size_t)row * 128 + c8);
    __half2 z = __float2half2_rn(0.f);
    uint32_t* hp = reinterpret_cast<uint32_t*>(&hv);
    int cb = c8 >> 1;
#pragma unroll
    for (int j = 0; j < 4; j++) {
        __half2 h = *reinterpret_cast<__half2*>(&hp[j]);
        __half2 o = __hmax2(__hfma2(h, ssc[cb + j], ssh[cb + j]), z);
        hp[j] = *reinterpret_cast<uint32_t*>(&o);
    }
    *(uint4*)(g_h2 + (size_t)row * 128 + c8) = hv;
}

// ---------------- pooling (final BN inline) + head ----------------
__global__ void k_pool(const int* __restrict__ batch, const float* __restrict__ gammas,
                       const float* __restrict__ betas, int l, int N, int nlen, float invN) {
    int c = threadIdx.x;
    int n0 = blockIdx.x * nlen, n1 = min(N, n0 + nlen);
    if (n0 >= n1) return;
    float sm = g_bnsum[l * 128 + c], sq = g_bnsq[l * 128 + c];
    float mu = sm * invN;
    float var = sq * invN - mu * mu;
    float sc = rsqrtf(var + 1e-5f) * __ldg(gammas + l * 128 + c);
    float sh = __ldg(betas + l * 128 + c) - mu * sc;
    int cur = __ldg(batch + n0);
    float acc = 0.f;
    int cnt = 0;
    for (int n = n0; n < n1; n++) {
        int gg = __ldg(batch + n);
        if (gg != cur) {
            atomicAdd(g_acc + (size_t)cur * 128 + c, acc);
            if (c == 0) atomicAdd(g_cnt + cur, cnt);
            acc = 0.f; cnt = 0; cur = gg;
        }
        float hv = __half2float(g_h[(size_t)n * 128 + c]);
        float v = fmaxf(fmaf(hv, sc, sh), 0.f);
        acc += v;
        cnt++;
    }
    atomicAdd(g_acc + (size_t)cur * 128 + c, acc);
    if (c == 0) atomicAdd(g_cnt + cur, cnt);
}

__global__ void k_final(const float* __restrict__ fw, const float* __restrict__ fb,
                        const float* __restrict__ beta, const float* __restrict__ rf,
                        float* __restrict__ out, int G) {
    int wid = threadIdx.x >> 5, lane = threadIdx.x & 31;
    int g = blockIdx.x * 4 + wid;
    if (g >= G) return;
    float4 a = ((const float4*)(g_acc + (size_t)g * 128))[lane];
    float4 w = ((const float4*)fw)[lane];
    float dot = a.x * w.x + a.y * w.y + a.z * w.z + a.w * w.w;
#pragma unroll
    for (int o = 16; o > 0; o >>= 1) dot += __shfl_down_sync(0xFFFFFFFFu, dot, o);
    if (lane == 0) {
        float cntf = fmaxf((float)g_cnt[g], 1.f);
        float pred = dot / cntf + fb[0];
        float sg = 1.f / (1.f + __expf(-pred));
        float b = beta[0];
        out[g] = (1.f - b) * sg + b * rf[g];
    }
}

// ---------------- restore zeroed state for next (graph-replayed) call --------------
__global__ void k_cleanup(int N, int G) {
    int i = blockIdx.x * blockDim.x + threadIdx.x;
    int stride = gridDim.x * blockDim.x;
    for (int j = i; j < N; j += stride) { g_deg[j] = 0; g_cursor[j] = 0; }
    for (int j = i; j < G * 128; j += stride) g_acc[j] = 0.f;
    for (int j = i; j < G; j += stride) g_cnt[j] = 0;
    for (int j = i; j < 1024; j += stride) { g_bnsum[j] = 0.f; g_bnsq[j] = 0.f; }
    for (int j = i; j < 128; j += stride) g_scanflag[j] = 0;
}

// ---------------- launch ----------------
extern "C" void kernel_launch(void* const* d_in, const int* in_sizes, int n_in,
                              void* d_out, int out_size) {
    const int*   x      = (const int*)d_in[0];
    const int*   ei     = (const int*)d_in[1];
    const int*   ea     = (const int*)d_in[2];
    const int*   batch  = (const int*)d_in[3];
    const float* rf     = (const float*)d_in[4];
    const float* aemb   = (const float*)d_in[5];
    const float* bemb   = (const float*)d_in[6];
    const float* convw  = (const float*)d_in[7];
    const float* convb  = (const float*)d_in[8];
    const float* ts     = (const float*)d_in[9];
    const float* gammas = (const float*)d_in[10];
    const float* betas  = (const float*)d_in[11];
    const float* fw     = (const float*)d_in[12];
    const float* fb     = (const float*)d_in[13];
    const float* beta   = (const float*)d_in[14];
    float* out = (float*)d_out;

    int N = in_sizes[0] / 9;
    int E = in_sizes[1] / 2;
    int G = in_sizes[4];
    int L = in_sizes[9];
    float invN = 1.f / (float)N;

    cudaFuncSetAttribute(k_gemm, cudaFuncAttributeMaxDynamicSharedMemorySize, GEMM_SMEM);

    int agg_grid = (N + 3) / 4;
    int gemm_grid = (N + 127) / 128;
    int prep_grid = (N * 16 + 255) / 256;
    int nb = (N + 1023) / 1024;   // 98 blocks <= 148 SMs (lookback-safe)

    k_init<<<L * 128 + 512 + 2048 + 2048, 128>>>(x, aemb, bemb, convw, ei, N, E, L);
    k_scan<<<nb, 1024>>>(N, E);
    k_scatter<<<(E + 255) / 256, 256>>>(ei, ea, E);

    k_agg<<<agg_grid, 128>>>(ts, 0, N);            // launch index 3 -> ncu target
    k_gemm<<<gemm_grid, 256, GEMM_SMEM>>>(convb, 0, 0, N);

    for (int l = 1; l < L; l++) {
        k_prep<<<prep_grid, 256>>>(gammas, betas, l - 1, N, invN);
        k_agg<<<agg_grid, 128>>>(ts, l, N);
        k_gemm<<<gemm_grid, 256, GEMM_SMEM>>>(convb, l, 1, N);
    }

    int P = 512;
    int nlen = (N + P - 1) / P;
    k_pool<<<P, 128>>>(batch, gammas, betas, L - 1, N, nlen, invN);
    k_final<<<(G + 3) / 4, 128>>>(fw, fb, beta, rf, out, G);
    k_cleanup<<<512, 256>>>(N, G);
}

// round 9
// speedup vs baseline: 2.8227x; 1.0341x over previous
#include <cuda_runtime.h>
#include <cuda_fp16.h>
#include <cstdint>

#define MAXN 131072
#define MAXE 655360
#define GMAX 1024

// ---------------- static scratch (zero-initialized at module load) ----------------
__device__ __half  g_h[(size_t)MAXN * 128];        // residual stream (fp16)
__device__ __half  g_h2[(size_t)MAXN * 128];       // s * relu(BN(h)) (fp16)
__device__ __half  g_t[(size_t)MAXN * 128];        // GEMM A operand (fp16)
__device__ __half  g_ecombB[512 * 128];            // combined bond-emb base (fp16)
__device__ __half  g_ecomb[512 * 128];             // per-layer scaled: e*s - 6
__device__ int2    g_epack[MAXE];                  // {src*256, combo*256}, CSR order
__device__ int     g_rowptr[MAXN + 1];
__device__ int     g_deg[MAXN];                    // zeroed by pool-extra blocks
__device__ int     g_cursor[MAXN];                 // zeroed by pool-extra blocks
__device__ int     g_scanagg[128];
__device__ int     g_scanpre[128];
__device__ volatile int g_scanflag[128];           // zeroed by pool-extra blocks
__device__ __half  g_Wt[8 * 128 * 128];            // Wt[l][n][k] = W[l][k][n] (fp16)
__device__ float   g_bnsum[8 * 128];               // zeroed by k_final blocks 0-7
__device__ float   g_bnsq[8 * 128];
__device__ float   g_acc[(size_t)GMAX * 128];      // zeroed by k_final after read
__device__ int     g_cnt[GMAX];

// ---------------- helpers ----------------
__device__ __forceinline__ uint32_t smem_u32(const void* p) {
    uint32_t a;
    asm("{ .reg .u64 t; cvta.to.shared.u64 t, %1; cvt.u32.u64 %0, t; }" : "=r"(a) : "l"(p));
    return a;
}

#define LDMATRIX_X4(r0, r1, r2, r3, addr) \
    asm volatile("ldmatrix.sync.aligned.m8n8.x4.shared.b16 {%0,%1,%2,%3}, [%4];" \
                 : "=r"(r0), "=r"(r1), "=r"(r2), "=r"(r3) : "r"(addr))

#define MMA_F16(c, a0, a1, a2, a3, b0, b1) \
    asm volatile("mma.sync.aligned.m16n8k16.row.col.f32.f16.f16.f32 " \
                 "{%0,%1,%2,%3}, {%4,%5,%6,%7}, {%8,%9}, {%0,%1,%2,%3};" \
                 : "+f"((c)[0]), "+f"((c)[1]), "+f"((c)[2]), "+f"((c)[3]) \
                 : "r"(a0), "r"(a1), "r"(a2), "r"(a3), "r"(b0), "r"(b1))

#define EX2_F16X2(dst, src) \
    asm("ex2.approx.f16x2 %0, %1;" : "=r"(dst) : "r"(src))

#define LOG2E 1.44269504088896f

// ---------------- fused init: convW | ecomb | h0 (warp/node) | degree hist --------
__global__ void __launch_bounds__(128) k_init(const int* __restrict__ x,
                                              const float* __restrict__ aemb,
                                              const float* __restrict__ bemb,
                                              const float* __restrict__ w,
                                              const int* __restrict__ ei,
                                              const float* __restrict__ ts,
                                              int N, int E, int L) {
    int b = blockIdx.x;
    int tid = threadIdx.x;
    int gcw = L * 128;
    if (b < gcw) {                       // transpose conv weights -> fp16
        int i = b * 128 + tid;
        int l = i >> 14, r = i & 16383, n = r >> 7, k = r & 127;
        g_Wt[i] = __float2half(w[(l << 14) + (k << 7) + n]);
        return;
    }
    b -= gcw;
    if (b < 512) {                       // combined bond table: base + layer-0 scaled
        int a0 = b & 7, a1 = (b >> 3) & 7, a2 = (b >> 6) & 7;
        float s = __ldg(bemb + (0 * 8 + a0) * 128 + tid)
                + __ldg(bemb + (1 * 8 + a1) * 128 + tid)
                + __ldg(bemb + (2 * 8 + a2) * 128 + tid);
        float s0 = __ldg(ts) * LOG2E;
        g_ecombB[b * 128 + tid] = __float2half(s);
        g_ecomb[b * 128 + tid] = __float2half(s * s0 - 6.0f);
        return;
    }
    b -= 512;
    if (b < 1024) {                      // atom encoder, warp per node, float4
        int wid = tid >> 5, lane = tid & 31;
        float s0 = __ldg(ts) * LOG2E;
        for (int n = b * 4 + wid; n < N; n += 4096) {
            float4 sum = make_float4(0.f, 0.f, 0.f, 0.f);
#pragma unroll
            for (int f = 0; f < 9; f++) {
                int xi = __ldg(x + n * 9 + f);
                float4 v = __ldg((const float4*)(aemb + ((size_t)f * 64 + xi) * 128) + lane);
                sum.x += v.x; sum.y += v.y; sum.z += v.z; sum.w += v.w;
            }
            __half2 a01 = __floats2half2_rn(sum.x, sum.y);
            __half2 a23 = __floats2half2_rn(sum.z, sum.w);
            uint2 hv;
            hv.x = *reinterpret_cast<uint32_t*>(&a01);
            hv.y = *reinterpret_cast<uint32_t*>(&a23);
            *(uint2*)(g_h + (size_t)n * 128 + lane * 4) = hv;
            __half2 b01 = __floats2half2_rn(sum.x * s0, sum.y * s0);
            __half2 b23 = __floats2half2_rn(sum.z * s0, sum.w * s0);
            uint2 h2v;
            h2v.x = *reinterpret_cast<uint32_t*>(&b01);
            h2v.y = *reinterpret_cast<uint32_t*>(&b23);
            *(uint2*)(g_h2 + (size_t)n * 128 + lane * 4) = h2v;
        }
        return;
    }
    b -= 1024;
    for (int e = b * 128 + tid; e < E; e += 2048 * 128)
        atomicAdd(g_deg + __ldg(ei + E + e), 1);
}

// ---------------- single-kernel decoupled-lookback exclusive scan ----------------
__global__ void __launch_bounds__(1024) k_scan(int N, int E) {
    __shared__ int warp_tot[32];
    __shared__ int s_prefix;
    int b = blockIdx.x, tid = threadIdx.x, lane = tid & 31, wid = tid >> 5;
    int i = b * 1024 + tid;
    int v = (i < N) ? g_deg[i] : 0;
    int xv = v;
#pragma unroll
    for (int o = 1; o < 32; o <<= 1) {
        int y = __shfl_up_sync(0xFFFFFFFFu, xv, o);
        if (lane >= o) xv += y;
    }
    if (lane == 31) warp_tot[wid] = xv;
    __syncthreads();
    if (wid == 0) {
        int wv = warp_tot[lane];
#pragma unroll
        for (int o = 1; o < 32; o <<= 1) {
            int y = __shfl_up_sync(0xFFFFFFFFu, wv, o);
            if (lane >= o) wv += y;
        }
        warp_tot[lane] = wv;
    }
    __syncthreads();
    int woff = wid ? warp_tot[wid - 1] : 0;
    int incl = woff + xv;
    int total = warp_tot[31];
    if (tid == 0) {
        g_scanagg[b] = total;
        __threadfence();
        g_scanflag[b] = 1;
        int sum = 0;
        for (int j = b - 1; j >= 0; j--) {
            int f;
            while ((f = g_scanflag[j]) == 0) {}
            if (f == 2) { sum += ((volatile int*)g_scanpre)[j]; break; }
            sum += ((volatile int*)g_scanagg)[j];
        }
        g_scanpre[b] = sum + total;
        __threadfence();
        g_scanflag[b] = 2;
        s_prefix = sum;
    }
    __syncthreads();
    int excl = s_prefix + incl - v;
    if (i < N) g_rowptr[i] = excl;
    if (i == N - 1) g_rowptr[N] = E;
}

// ---------------- scatter edges into CSR order (byte-offset packed) ----------------
__global__ void k_scatter(const int* __restrict__ ei, const int* __restrict__ ea, int E) {
    int e = blockIdx.x * blockDim.x + threadIdx.x;
    if (e >= E) return;
    int d = __ldg(ei + E + e);
    int pos = g_rowptr[d] + atomicAdd(g_cursor + d, 1);
    int a0 = __ldg(ea + e * 3 + 0), a1 = __ldg(ea + e * 3 + 1), a2 = __ldg(ea + e * 3 + 2);
    g_epack[pos] = make_int2(__ldg(ei + e) << 8, (a0 + a1 * 8 + a2 * 64) << 8);
}

// ---------------- softmax aggregation: folded scale+bias, all-f16x2 ----------------
__global__ void __launch_bounds__(128) k_agg(const float* __restrict__ ts, int l, int N) {
    int gw = (blockIdx.x << 2) + (threadIdx.x >> 5);
    if (gw >= N) return;
    int lane = threadIdx.x & 31;
    const char* ph = (const char*)g_h2 + lane * 8;
    const char* pe = (const char*)g_ecomb + lane * 8;
    float sscale = __ldg(ts + l) * LOG2E;
    float invs = 1.0f / sscale;
    __half2 neg6 = __float2half2_rn(-6.0f);
    __half2 z = __float2half2_rn(0.f);

    uint2 hu = *(const uint2*)(ph + (size_t)gw * 256);
    float2 hi01 = __half22float2(*reinterpret_cast<__half2*>(&hu.x));
    float2 hi23 = __half22float2(*reinterpret_cast<__half2*>(&hu.y));

    int p0 = __ldg(g_rowptr + gw), p1 = __ldg(g_rowptr + gw + 1);
    __half2 s01 = z, s23 = z, w01 = z, w23 = z;

#pragma unroll 2
    for (int p = p0; p < p1; p++) {
        int2 ep = __ldg(g_epack + p);
        uint2 su = *(const uint2*)(ph + ep.x);
        uint2 eu = *(const uint2*)(pe + ep.y);
        // qb = max(s*(h+e) - 6, -6) = s*relu(h+e) - 6   (e-table carries the -6)
        __half2 qb01 = __hmax2(__hadd2(*reinterpret_cast<__half2*>(&su.x),
                                       *reinterpret_cast<__half2*>(&eu.x)), neg6);
        __half2 qb23 = __hmax2(__hadd2(*reinterpret_cast<__half2*>(&su.y),
                                       *reinterpret_cast<__half2*>(&eu.y)), neg6);
        uint32_t x01u, x23u;
        EX2_F16X2(x01u, *reinterpret_cast<uint32_t*>(&qb01));
        EX2_F16X2(x23u, *reinterpret_cast<uint32_t*>(&qb23));
        __half2 x01 = *reinterpret_cast<__half2*>(&x01u);
        __half2 x23 = *reinterpret_cast<__half2*>(&x23u);
        s01 = __hadd2(s01, x01);
        s23 = __hadd2(s23, x23);
        w01 = __hfma2(x01, qb01, w01);
        w23 = __hfma2(x23, qb23, w23);
    }

    float2 sf01 = __half22float2(s01), sf23 = __half22float2(s23);
    float2 wf01 = __half22float2(w01), wf23 = __half22float2(w23);
    // aggr*s = (w + 6*s_acc)/s_acc ;  o = (h'' + aggr*s) / s
    float r0 = fmaf(6.f, sf01.x, wf01.x) / (sf01.x + 1e-16f);
    float r1 = fmaf(6.f, sf01.y, wf01.y) / (sf01.y + 1e-16f);
    float r2 = fmaf(6.f, sf23.x, wf23.x) / (sf23.x + 1e-16f);
    float r3 = fmaf(6.f, sf23.y, wf23.y) / (sf23.y + 1e-16f);
    float o0 = (hi01.x + r0) * invs;
    float o1 = (hi01.y + r1) * invs;
    float o2 = (hi23.x + r2) * invs;
    float o3 = (hi23.y + r3) * invs;

    __half2 t01 = __floats2half2_rn(o0, o1);
    __half2 t23 = __floats2half2_rn(o2, o3);
    uint2 st;
    st.x = *reinterpret_cast<uint32_t*>(&t01);
    st.y = *reinterpret_cast<uint32_t*>(&t23);
    *(uint2*)(g_t + (size_t)gw * 128 + lane * 4) = st;
}

// ---------------- mma.sync GEMM + fused BN stats (h fp16) ----------------
#define GEMM_SMEM (2 * 128 * 272 + 1024)

__global__ void __launch_bounds__(256) k_gemm(const float* __restrict__ conv_b,
                                              int l, int add_res, int N) {
    extern __shared__ char smem[];
    char* sA = smem;
    char* sB = smem + 128 * 272;
    float* sbn = (float*)(smem + 2 * 128 * 272);
    int tid = threadIdx.x;
    int node0 = blockIdx.x * 128;

    if (tid < 256) sbn[tid] = 0.f;

    const uint4* asrc = (const uint4*)(g_t + (size_t)node0 * 128);
    const uint4* bsrc = (const uint4*)(g_Wt + (size_t)l * 16384);
#pragma unroll
    for (int i = tid; i < 2048; i += 256) {
        int row = i >> 4, cq = i & 15;
        *(uint4*)(sA + row * 272 + cq * 16) = asrc[i];
        *(uint4*)(sB + row * 272 + cq * 16) = bsrc[i];
    }
    __syncthreads();

    int wid = tid >> 5, lane = tid & 31;
    int wm = wid >> 1, wn = wid & 1;
    uint32_t sab = smem_u32(sA), sbb = smem_u32(sB);

    float acc[2][8][4];
#pragma unroll
    for (int mt = 0; mt < 2; mt++)
#pragma unroll
        for (int nt = 0; nt < 8; nt++)
#pragma unroll
            for (int q = 0; q < 4; q++) acc[mt][nt][q] = 0.f;

    int lrow = lane & 15, lhalf = (lane >> 4) << 3;

#pragma unroll
    for (int ks = 0; ks < 8; ks++) {
        int k0 = ks * 16;
        uint32_t a[2][4];
#pragma unroll
        for (int mt = 0; mt < 2; mt++) {
            int r = wm * 32 + mt * 16 + lrow;
            uint32_t addr = sab + r * 272 + (k0 + lhalf) * 2;
            LDMATRIX_X4(a[mt][0], a[mt][1], a[mt][2], a[mt][3], addr);
        }
        uint32_t bq[4][4];
#pragma unroll
        for (int nq = 0; nq < 4; nq++) {
            int nr = wn * 64 + nq * 16 + lrow;
            uint32_t addr = sbb + nr * 272 + (k0 + lhalf) * 2;
            LDMATRIX_X4(bq[nq][0], bq[nq][1], bq[nq][2], bq[nq][3], addr);
        }
#pragma unroll
        for (int mt = 0; mt < 2; mt++)
#pragma unroll
            for (int nq = 0; nq < 4; nq++) {
                MMA_F16(acc[mt][nq * 2 + 0], a[mt][0], a[mt][1], a[mt][2], a[mt][3],
                        bq[nq][0], bq[nq][2]);
                MMA_F16(acc[mt][nq * 2 + 1], a[mt][0], a[mt][1], a[mt][2], a[mt][3],
                        bq[nq][1], bq[nq][3]);
            }
    }

    int qrow = lane >> 2, qcol = (lane & 3) * 2;
    float colS[16], colQ[16];
#pragma unroll
    for (int i = 0; i < 16; i++) { colS[i] = 0.f; colQ[i] = 0.f; }

#pragma unroll
    for (int mt = 0; mt < 2; mt++) {
#pragma unroll
        for (int nt = 0; nt < 8; nt++) {
            int col = wn * 64 + nt * 8 + qcol;
            float2 bv = *(const float2*)(conv_b + l * 128 + col);
            int row0 = node0 + wm * 32 + mt * 16 + qrow;
#pragma unroll
            for (int hh = 0; hh < 2; hh++) {
                int row = row0 + hh * 8;
                if (row < N) {
                    __half* dst = g_h + (size_t)row * 128 + col;
                    float vx = acc[mt][nt][hh * 2 + 0] + bv.x;
                    float vy = acc[mt][nt][hh * 2 + 1] + bv.y;
                    if (add_res) {
                        float2 r = __half22float2(*(const __half2*)dst);
                        vx += r.x; vy += r.y;
                    }
                    *(__half2*)dst = __floats2half2_rn(vx, vy);
                    colS[nt * 2 + 0] += vx;
                    colQ[nt * 2 + 0] = fmaf(vx, vx, colQ[nt * 2 + 0]);
                    colS[nt * 2 + 1] += vy;
                    colQ[nt * 2 + 1] = fmaf(vy, vy, colQ[nt * 2 + 1]);
                }
            }
        }
    }

#pragma unroll
    for (int i = 0; i < 16; i++) {
        float vs = colS[i], vq = colQ[i];
        vs += __shfl_xor_sync(0xFFFFFFFFu, vs, 4);
        vs += __shfl_xor_sync(0xFFFFFFFFu, vs, 8);
        vs += __shfl_xor_sync(0xFFFFFFFFu, vs, 16);
        vq += __shfl_xor_sync(0xFFFFFFFFu, vq, 4);
        vq += __shfl_xor_sync(0xFFFFFFFFu, vq, 8);
        vq += __shfl_xor_sync(0xFFFFFFFFu, vq, 16);
        if (lane < 4) {
            int col = wn * 64 + (i >> 1) * 8 + lane * 2 + (i & 1);
            atomicAdd(sbn + col, vs);
            atomicAdd(sbn + 128 + col, vq);
        }
    }
    __syncthreads();
    if (tid < 128) {
        atomicAdd(g_bnsum + l * 128 + tid, sbn[tid]);
        atomicAdd(g_bnsq + l * 128 + tid, sbn[128 + tid]);
    }
}

// ------ prep: h2 = s*relu(BN(h)) (scale folded), plus per-layer ecomb = eB*s - 6 ------
__global__ void __launch_bounds__(256) k_prep(const float* __restrict__ gammas,
                                              const float* __restrict__ betas,
                                              const float* __restrict__ ts,
                                              int l, int N, float invN, int hb) {
    int b = blockIdx.x;
    int tid = threadIdx.x;
    float s = __ldg(ts + l) * LOG2E;
    if (b >= hb) {                              // scaled edge table: 128 blocks
        int idx = (b - hb) * 256 + tid;         // half2 index, 32768 total
        __half2 e = ((const __half2*)g_ecombB)[idx];
        float2 ef = __half22float2(e);
        ((__half2*)g_ecomb)[idx] = __floats2half2_rn(ef.x * s - 6.f, ef.y * s - 6.f);
        return;
    }
    __shared__ __half2 ssc[64], ssh[64];
    if (tid < 64) {
        int cp = tid * 2;
        int ls = l - 1;                         // stats slot of previous layer
        float2 sm = *(const float2*)(g_bnsum + ls * 128 + cp);
        float2 sq = *(const float2*)(g_bnsq + ls * 128 + cp);
        float2 ga = *(const float2*)(gammas + ls * 128 + cp);
        float2 be = *(const float2*)(betas + ls * 128 + cp);
        float mu0 = sm.x * invN, mu1 = sm.y * invN;
        float va0 = sq.x * invN - mu0 * mu0, va1 = sq.y * invN - mu1 * mu1;
        float sc0 = rsqrtf(va0 + 1e-5f) * ga.x, sc1 = rsqrtf(va1 + 1e-5f) * ga.y;
        float sh0 = be.x - mu0 * sc0, sh1 = be.y - mu1 * sc1;
        ssc[tid] = __floats2half2_rn(sc0 * s, sc1 * s);   // fold s into BN affine
        ssh[tid] = __floats2half2_rn(sh0 * s, sh1 * s);
    }
    __syncthreads();
    int idx = b * 256 + tid;                    // N*16 units of 8 channels
    if (idx >= N * 16) return;
    int row = idx >> 4, c8 = (idx & 15) << 3;
    uint4 hv = *(const uint4*)(g_h + (size_t)row * 128 + c8);
    __half2 z = __float2half2_rn(0.f);
    uint32_t* hp = reinterpret_cast<uint32_t*>(&hv);
    int cb = c8 >> 1;
#pragma unroll
    for (int j = 0; j < 4; j++) {
        __half2 h = *reinterpret_cast<__half2*>(&hp[j]);
        __half2 o = __hmax2(__hfma2(h, ssc[cb + j], ssh[cb + j]), z);
        hp[j] = *reinterpret_cast<uint32_t*>(&o);
    }
    *(uint4*)(g_h2 + (size_t)row * 128 + c8) = hv;
}

// ---------------- pooling (final BN inline) + prologue-state cleanup ----------------
__global__ void k_pool(const int* __restrict__ batch, const float* __restrict__ gammas,
                       const float* __restrict__ betas, int l, int N, int nlen,
                       float invN, int P) {
    if ((int)blockIdx.x >= P) {                 // cleanup blocks (state unused by pool)
        int base = (blockIdx.x - P) * 128 + threadIdx.x;
        for (int j = base; j < N; j += 16 * 128) { g_deg[j] = 0; g_cursor[j] = 0; }
        if (base < 128) g_scanflag[base] = 0;
        return;
    }
    int c = threadIdx.x;
    int n0 = blockIdx.x * nlen, n1 = min(N, n0 + nlen);
    if (n0 >= n1) return;
    float sm = g_bnsum[l * 128 + c], sq = g_bnsq[l * 128 + c];
    float mu = sm * invN;
    float var = sq * invN - mu * mu;
    float sc = rsqrtf(var + 1e-5f) * __ldg(gammas + l * 128 + c);
    float sh = __ldg(betas + l * 128 + c) - mu * sc;
    int cur = __ldg(batch + n0);
    float acc = 0.f;
    int cnt = 0;
    for (int n = n0; n < n1; n++) {
        int gg = __ldg(batch + n);
        if (gg != cur) {
            atomicAdd(g_acc + (size_t)cur * 128 + c, acc);
            if (c == 0) atomicAdd(g_cnt + cur, cnt);
            acc = 0.f; cnt = 0; cur = gg;
        }
        float hv = __half2float(g_h[(size_t)n * 128 + c]);
        float v = fmaxf(fmaf(hv, sc, sh), 0.f);
        acc += v;
        cnt++;
    }
    atomicAdd(g_acc + (size_t)cur * 128 + c, acc);
    if (c == 0) atomicAdd(g_cnt + cur, cnt);
}

// ---------------- head + remaining cleanup ----------------
__global__ void k_final(const float* __restrict__ fw, const float* __restrict__ fb,
                        const float* __restrict__ beta, const float* __restrict__ rf,
                        float* __restrict__ out, int G) {
    int wid = threadIdx.x >> 5, lane = threadIdx.x & 31;
    if (blockIdx.x < 8) {                       // BN stats cleanup (read by nobody now)
        g_bnsum[blockIdx.x * 128 + threadIdx.x] = 0.f;
        g_bnsq[blockIdx.x * 128 + threadIdx.x] = 0.f;
    }
    int g = blockIdx.x * 4 + wid;
    if (g >= G) return;
    float4 a = ((const float4*)(g_acc + (size_t)g * 128))[lane];
    float4 w = ((const float4*)fw)[lane];
    float dot = a.x * w.x + a.y * w.y + a.z * w.z + a.w * w.w;
#pragma unroll
    for (int o = 16; o > 0; o >>= 1) dot += __shfl_down_sync(0xFFFFFFFFu, dot, o);
    int cntv = g_cnt[g];
    // zero accumulators for the next graph replay (after reading)
    ((float4*)(g_acc + (size_t)g * 128))[lane] = make_float4(0.f, 0.f, 0.f, 0.f);
    if (lane == 0) {
        g_cnt[g] = 0;
        float cntf = fmaxf((float)cntv, 1.f);
        float pred = dot / cntf + fb[0];
        float sg = 1.f / (1.f + __expf(-pred));
        float b = beta[0];
        out[g] = (1.f - b) * sg + b * rf[g];
    }
}

// ---------------- launch ----------------
extern "C" void kernel_launch(void* const* d_in, const int* in_sizes, int n_in,
                              void* d_out, int out_size) {
    const int*   x      = (const int*)d_in[0];
    const int*   ei     = (const int*)d_in[1];
    const int*   ea     = (const int*)d_in[2];
    const int*   batch  = (const int*)d_in[3];
    const float* rf     = (const float*)d_in[4];
    const float* aemb   = (const float*)d_in[5];
    const float* bemb   = (const float*)d_in[6];
    const float* convw  = (const float*)d_in[7];
    const float* convb  = (const float*)d_in[8];
    const float* ts     = (const float*)d_in[9];
    const float* gammas = (const float*)d_in[10];
    const float* betas  = (const float*)d_in[11];
    const float* fw     = (const float*)d_in[12];
    const float* fb     = (const float*)d_in[13];
    const float* beta   = (const float*)d_in[14];
    float* out = (float*)d_out;

    int N = in_sizes[0] / 9;
    int E = in_sizes[1] / 2;
    int G = in_sizes[4];
    int L = in_sizes[9];
    float invN = 1.f / (float)N;

    cudaFuncSetAttribute(k_gemm, cudaFuncAttributeMaxDynamicSharedMemorySize, GEMM_SMEM);

    int agg_grid = (N + 3) / 4;
    int gemm_grid = (N + 127) / 128;
    int hb = (N * 16 + 255) / 256;
    int nb = (N + 1023) / 1024;   // 98 blocks <= 148 SMs (lookback-safe)

    k_init<<<L * 128 + 512 + 1024 + 2048, 128>>>(x, aemb, bemb, convw, ei, ts, N, E, L);
    k_scan<<<nb, 1024>>>(N, E);
    k_scatter<<<(E + 255) / 256, 256>>>(ei, ea, E);

    k_agg<<<agg_grid, 128>>>(ts, 0, N);            // launch index 3 -> ncu target
    k_gemm<<<gemm_grid, 256, GEMM_SMEM>>>(convb, 0, 0, N);

    for (int l = 1; l < L; l++) {
        k_prep<<<hb + 128, 256>>>(gammas, betas, ts, l, N, invN, hb);
        k_agg<<<agg_grid, 128>>>(ts, l, N);
        k_gemm<<<gemm_grid, 256, GEMM_SMEM>>>(convb, l, 1, N);
    }

    int P = 512;
    int nlen = (N + P - 1) / P;
    k_pool<<<P + 16, 128>>>(batch, gammas, betas, L - 1, N, nlen, invN, P);
    k_final<<<(G + 3) / 4, 128>>>(fw, fb, beta, rf, out, G);
}